// round 3
// baseline (speedup 1.0000x reference)
#include <cuda_runtime.h>
#include <math.h>

#define N_NODES 100000
#define FEAT 128

// Scratch (allocation-free rule: __device__ globals)
__device__ float g_agg[(size_t)N_NODES * FEAT];
__device__ float g_cnt[N_NODES];
__device__ float g_h[(size_t)N_NODES * FEAT];
__device__ int   g_is64;

// ---------------------------------------------------------------------------
// Detect whether edge_index is int64 or int32.
// If int64 (values < 2^31, nonnegative), every odd 32-bit word is 0.
// ---------------------------------------------------------------------------
__global__ void detect_kernel(const unsigned int* __restrict__ e) {
    __shared__ int nz;
    if (threadIdx.x == 0) nz = 0;
    __syncthreads();
    unsigned int acc = 0;
    for (int i = threadIdx.x; i < 1024; i += blockDim.x)
        acc |= e[2 * i + 1];
    if (acc) atomicOr(&nz, 1);
    __syncthreads();
    if (threadIdx.x == 0) g_is64 = (nz == 0) ? 1 : 0;
}

// ---------------------------------------------------------------------------
// Zero agg (and optionally cnt)
// ---------------------------------------------------------------------------
__global__ void zero_kernel(int zero_cnt) {
    size_t idx = (size_t)blockIdx.x * blockDim.x + threadIdx.x;
    size_t stride = (size_t)gridDim.x * blockDim.x;
    float4 z = make_float4(0.f, 0.f, 0.f, 0.f);
    float4* p = (float4*)g_agg;
    size_t n4 = (size_t)N_NODES * FEAT / 4;
    for (size_t i = idx; i < n4; i += stride) p[i] = z;
    if (zero_cnt)
        for (size_t i = idx; i < N_NODES; i += stride) g_cnt[i] = 0.f;
}

// ---------------------------------------------------------------------------
// Scatter-add: one warp per edge, each lane handles one float4 (4 features).
// feat = x (use_h==0) or g_h (use_h==1).
// ---------------------------------------------------------------------------
__global__ void scatter_kernel(const void* __restrict__ edges,
                               const float* __restrict__ x,
                               int E, int use_h, int add_cnt) {
    long long gid = (long long)blockIdx.x * blockDim.x + threadIdx.x;
    int lane = (int)(gid & 31);
    long long e = gid >> 5;
    if (e >= E) return;

    int src, dst;
    if (g_is64) {
        const long long* p = (const long long*)edges;
        src = (int)p[e];
        dst = (int)p[E + e];
    } else {
        const int* p = (const int*)edges;
        src = p[e];
        dst = p[E + e];
    }

    const float* feat = use_h ? g_h : x;
    float4 v = ((const float4*)(feat + (size_t)src * FEAT))[lane];
    float* a = g_agg + (size_t)dst * FEAT + lane * 4;
    atomicAdd(a + 0, v.x);
    atomicAdd(a + 1, v.y);
    atomicAdd(a + 2, v.z);
    atomicAdd(a + 3, v.w);
    if (add_cnt && lane == 0) atomicAdd(&g_cnt[dst], 1.0f);
}

// ---------------------------------------------------------------------------
// Layer 1 GEMM: h = relu( mean @ W1l^T + b1l + x @ W1r^T )
// Combined K = 256 (mean || x). Tile: 64 nodes x 128 outs per block,
// 256 threads, each thread computes 4 nodes x 8 outs.
// Weights staged k-major in smem with row stride 132 (pad 4) so the
// transpose-on-store is only 4-way bank conflicted and float4 reads stay
// 16B-aligned (132 floats = 528B = 33*16).
// ---------------------------------------------------------------------------
#define L1_WS 132
#define L1_SMEM ((64 * 256 + 256 * L1_WS) * 4)

__global__ __launch_bounds__(256, 1)
void gemm1_kernel(const float* __restrict__ x,
                  const float* __restrict__ Wl,
                  const float* __restrict__ bl,
                  const float* __restrict__ Wr) {
    extern __shared__ float sm[];
    float* in_s = sm;              // [64][256]
    float* w_s = sm + 64 * 256;    // [256][132]

    int tid = threadIdx.x;
    int base = blockIdx.x * 64;

    // Stage weights k-major: w_s[k][o] = Wl[o][k] (k<128) / Wr[o][k-128]
    for (int idx = tid; idx < 128 * 128; idx += 256) {
        int o = idx >> 7, k = idx & 127;
        w_s[k * L1_WS + o] = Wl[idx];
        w_s[(k + 128) * L1_WS + o] = Wr[idx];
    }
    // Stage inputs: [node][k], k<128 -> mean, k>=128 -> x
    for (int idx = tid; idx < 64 * 256; idx += 256) {
        int nl = idx >> 8, k = idx & 255;
        int g = base + nl;
        float v = 0.f;
        if (g < N_NODES) {
            if (k < 128) {
                float c = g_cnt[g];
                v = g_agg[(size_t)g * 128 + k] / fmaxf(c, 1.f);
            } else {
                v = x[(size_t)g * 128 + (k - 128)];
            }
        }
        in_s[nl * 256 + k] = v;
    }
    __syncthreads();

    int tx = tid & 15, ty = tid >> 4;
    int o0 = tx * 8, n0 = ty * 4;

    float acc[4][8];
#pragma unroll
    for (int j = 0; j < 8; j++) {
        float b = bl[o0 + j];
        acc[0][j] = b; acc[1][j] = b; acc[2][j] = b; acc[3][j] = b;
    }

    for (int k = 0; k < 256; k += 4) {
        float4 a0 = *(const float4*)&in_s[(n0 + 0) * 256 + k];
        float4 a1 = *(const float4*)&in_s[(n0 + 1) * 256 + k];
        float4 a2 = *(const float4*)&in_s[(n0 + 2) * 256 + k];
        float4 a3 = *(const float4*)&in_s[(n0 + 3) * 256 + k];
        const float* ap0 = (const float*)&a0;
        const float* ap1 = (const float*)&a1;
        const float* ap2 = (const float*)&a2;
        const float* ap3 = (const float*)&a3;
#pragma unroll
        for (int kk = 0; kk < 4; kk++) {
            float4 w0 = *(const float4*)&w_s[(k + kk) * L1_WS + o0];
            float4 w1 = *(const float4*)&w_s[(k + kk) * L1_WS + o0 + 4];
            const float* wp0 = (const float*)&w0;
            const float* wp1 = (const float*)&w1;
            float av0 = ap0[kk], av1 = ap1[kk], av2 = ap2[kk], av3 = ap3[kk];
#pragma unroll
            for (int j = 0; j < 4; j++) {
                acc[0][j] += av0 * wp0[j]; acc[0][4 + j] += av0 * wp1[j];
                acc[1][j] += av1 * wp0[j]; acc[1][4 + j] += av1 * wp1[j];
                acc[2][j] += av2 * wp0[j]; acc[2][4 + j] += av2 * wp1[j];
                acc[3][j] += av3 * wp0[j]; acc[3][4 + j] += av3 * wp1[j];
            }
        }
    }

#pragma unroll
    for (int i = 0; i < 4; i++) {
        int g = base + n0 + i;
        if (g >= N_NODES) continue;
        float4 r0, r1;
        r0.x = fmaxf(acc[i][0], 0.f); r0.y = fmaxf(acc[i][1], 0.f);
        r0.z = fmaxf(acc[i][2], 0.f); r0.w = fmaxf(acc[i][3], 0.f);
        r1.x = fmaxf(acc[i][4], 0.f); r1.y = fmaxf(acc[i][5], 0.f);
        r1.z = fmaxf(acc[i][6], 0.f); r1.w = fmaxf(acc[i][7], 0.f);
        *(float4*)&g_h[(size_t)g * 128 + o0] = r0;
        *(float4*)&g_h[(size_t)g * 128 + o0 + 4] = r1;
    }
}

// ---------------------------------------------------------------------------
// Layer 2 GEMM + log_softmax: out = logsoftmax( mean2 @ W2l^T + b2l + h @ W2r^T )
// K = 256 (mean2 || h), OUT = 64. Tile: 64 nodes x 64 outs per block,
// thread computes 4 nodes x 4 outs. Epilogue: per-row warp-shuffle lse.
// ---------------------------------------------------------------------------
#define L2_WS 68
#define L2_SMEM ((64 * 256 + 256 * L2_WS + 64 * 64) * 4)

__global__ __launch_bounds__(256, 1)
void gemm2_kernel(const float* __restrict__ Wl,
                  const float* __restrict__ bl,
                  const float* __restrict__ Wr,
                  float* __restrict__ out) {
    extern __shared__ float sm[];
    float* in_s = sm;                        // [64][256]
    float* w_s = sm + 64 * 256;              // [256][68]
    float* out_s = sm + 64 * 256 + 256 * L2_WS; // [64][64]

    int tid = threadIdx.x;
    int base = blockIdx.x * 64;

    for (int idx = tid; idx < 64 * 128; idx += 256) {
        int o = idx >> 7, k = idx & 127;
        w_s[k * L2_WS + o] = Wl[idx];
        w_s[(k + 128) * L2_WS + o] = Wr[idx];
    }
    for (int idx = tid; idx < 64 * 256; idx += 256) {
        int nl = idx >> 8, k = idx & 255;
        int g = base + nl;
        float v = 0.f;
        if (g < N_NODES) {
            if (k < 128) {
                float c = g_cnt[g];
                v = g_agg[(size_t)g * 128 + k] / fmaxf(c, 1.f);
            } else {
                v = g_h[(size_t)g * 128 + (k - 128)];
            }
        }
        in_s[nl * 256 + k] = v;
    }
    __syncthreads();

    int tx = tid & 15, ty = tid >> 4;
    int o0 = tx * 4, n0 = ty * 4;

    float acc[4][4];
#pragma unroll
    for (int j = 0; j < 4; j++) {
        float b = bl[o0 + j];
        acc[0][j] = b; acc[1][j] = b; acc[2][j] = b; acc[3][j] = b;
    }

    for (int k = 0; k < 256; k += 4) {
        float4 a0 = *(const float4*)&in_s[(n0 + 0) * 256 + k];
        float4 a1 = *(const float4*)&in_s[(n0 + 1) * 256 + k];
        float4 a2 = *(const float4*)&in_s[(n0 + 2) * 256 + k];
        float4 a3 = *(const float4*)&in_s[(n0 + 3) * 256 + k];
        const float* ap0 = (const float*)&a0;
        const float* ap1 = (const float*)&a1;
        const float* ap2 = (const float*)&a2;
        const float* ap3 = (const float*)&a3;
#pragma unroll
        for (int kk = 0; kk < 4; kk++) {
            float4 w0 = *(const float4*)&w_s[(k + kk) * L2_WS + o0];
            const float* wp = (const float*)&w0;
            float av0 = ap0[kk], av1 = ap1[kk], av2 = ap2[kk], av3 = ap3[kk];
#pragma unroll
            for (int j = 0; j < 4; j++) {
                acc[0][j] += av0 * wp[j];
                acc[1][j] += av1 * wp[j];
                acc[2][j] += av2 * wp[j];
                acc[3][j] += av3 * wp[j];
            }
        }
    }

#pragma unroll
    for (int i = 0; i < 4; i++) {
        float4 r;
        r.x = acc[i][0]; r.y = acc[i][1]; r.z = acc[i][2]; r.w = acc[i][3];
        *(float4*)&out_s[(n0 + i) * 64 + o0] = r;
    }
    __syncthreads();

    // log_softmax per row of 64 classes: 8 warps, 8 rows each, 2 vals/lane
    int w = tid >> 5, lane = tid & 31;
    for (int r = 0; r < 8; r++) {
        int row = w * 8 + r;
        int g = base + row;
        if (g >= N_NODES) continue;
        float v0 = out_s[row * 64 + lane];
        float v1 = out_s[row * 64 + lane + 32];
        float m = fmaxf(v0, v1);
#pragma unroll
        for (int off = 16; off > 0; off >>= 1)
            m = fmaxf(m, __shfl_xor_sync(0xffffffffu, m, off));
        float s = expf(v0 - m) + expf(v1 - m);
#pragma unroll
        for (int off = 16; off > 0; off >>= 1)
            s += __shfl_xor_sync(0xffffffffu, s, off);
        float lse = m + logf(s);
        out[(size_t)g * 64 + lane] = v0 - lse;
        out[(size_t)g * 64 + lane + 32] = v1 - lse;
    }
}

// ---------------------------------------------------------------------------
// Launch
// ---------------------------------------------------------------------------
extern "C" void kernel_launch(void* const* d_in, const int* in_sizes, int n_in,
                              void* d_out, int out_size) {
    const float* x   = (const float*)d_in[0];
    const void*  edg = d_in[1];
    const float* W1l = (const float*)d_in[2];
    const float* b1l = (const float*)d_in[3];
    const float* W1r = (const float*)d_in[4];
    const float* W2l = (const float*)d_in[5];
    const float* b2l = (const float*)d_in[6];
    const float* W2r = (const float*)d_in[7];
    float* out = (float*)d_out;

    int E = in_sizes[1] / 2;

    cudaFuncSetAttribute(gemm1_kernel,
                         cudaFuncAttributeMaxDynamicSharedMemorySize, L1_SMEM);
    cudaFuncSetAttribute(gemm2_kernel,
                         cudaFuncAttributeMaxDynamicSharedMemorySize, L2_SMEM);

    int gemm_blocks = (N_NODES + 63) / 64;
    long long sthreads = (long long)E * 32;
    int sblocks = (int)((sthreads + 255) / 256);

    detect_kernel<<<1, 256>>>((const unsigned int*)edg);

    // Layer 1
    zero_kernel<<<2048, 256>>>(1);
    scatter_kernel<<<sblocks, 256>>>(edg, x, E, /*use_h=*/0, /*add_cnt=*/1);
    gemm1_kernel<<<gemm_blocks, 256, L1_SMEM>>>(x, W1l, b1l, W1r);

    // Layer 2
    zero_kernel<<<2048, 256>>>(0);
    scatter_kernel<<<sblocks, 256>>>(edg, x, E, /*use_h=*/1, /*add_cnt=*/0);
    gemm2_kernel<<<gemm_blocks, 256, L2_SMEM>>>(W2l, b2l, W2r, out);
}

// round 4
// speedup vs baseline: 2.7768x; 2.7768x over previous
#include <cuda_runtime.h>
#include <math.h>

#define N_NODES 100000
#define E_MAX   1600000

// ---------------------------------------------------------------------------
// Scratch (__device__ globals: allocation-free rule)
// ---------------------------------------------------------------------------
__device__ __align__(16) float g_agg[(size_t)N_NODES * 128]; // mean features
__device__ __align__(16) float g_h[(size_t)N_NODES * 128];   // layer-1 output
__device__ int   g_row[N_NODES + 1];   // CSR row_ptr (by dst)
__device__ int   g_cur[N_NODES];       // counts, then fill cursor
__device__ int   g_col[E_MAX];         // CSR col (src ids)
__device__ float g_inv[N_NODES];       // 1/max(deg,1)
__device__ __align__(16) float g_wt1[256 * 128]; // k-major [k][o]: W1l||W1r
__device__ __align__(16) float g_wt2[256 * 64];  // k-major [k][o]: W2l||W2r
__device__ int   g_is64;

// ---------------------------------------------------------------------------
// Packed f32x2 helpers (Blackwell FFMA2 — PTX-only)
// ---------------------------------------------------------------------------
__device__ __forceinline__ void fma2(unsigned long long& d,
                                     unsigned long long a,
                                     unsigned long long b) {
    asm("fma.rn.f32x2 %0, %1, %2, %0;" : "+l"(d) : "l"(a), "l"(b));
}
__device__ __forceinline__ unsigned long long pk2(float x, float y) {
    unsigned long long r;
    asm("mov.b64 %0, {%1, %2};" : "=l"(r) : "f"(x), "f"(y));
    return r;
}
__device__ __forceinline__ void up2(unsigned long long v, float& x, float& y) {
    asm("mov.b64 {%0, %1}, %2;" : "=f"(x), "=f"(y) : "l"(v));
}

// ---------------------------------------------------------------------------
// int64 vs int32 edge dtype detection (odd 32-bit words all zero => int64)
// ---------------------------------------------------------------------------
__global__ void detect_kernel(const unsigned int* __restrict__ e) {
    __shared__ int nz;
    if (threadIdx.x == 0) nz = 0;
    __syncthreads();
    unsigned int acc = 0;
    for (int i = threadIdx.x; i < 1024; i += blockDim.x)
        acc |= e[2 * i + 1];
    if (acc) atomicOr(&nz, 1);
    __syncthreads();
    if (threadIdx.x == 0) g_is64 = (nz == 0) ? 1 : 0;
}

__global__ void zero_cur_kernel() {
    int i = blockIdx.x * blockDim.x + threadIdx.x;
    if (i < N_NODES) g_cur[i] = 0;
}

// ---------------------------------------------------------------------------
// CSR build: histogram -> single-block scan -> fill
// ---------------------------------------------------------------------------
__global__ void hist_kernel(const void* __restrict__ edges, int E) {
    int i = blockIdx.x * blockDim.x + threadIdx.x;
    if (i >= E) return;
    int d = g_is64 ? (int)((const long long*)edges)[E + i]
                   : ((const int*)edges)[E + i];
    atomicAdd(&g_cur[d], 1);
}

__global__ void scan_kernel() {
    __shared__ int ssum[1024];
    int tid = threadIdx.x;
    const int CH = (N_NODES + 1023) / 1024;
    int beg = tid * CH;
    int end = min(beg + CH, N_NODES);
    int s = 0;
    for (int i = beg; i < end; i++) s += g_cur[i];
    ssum[tid] = s;
    __syncthreads();
    for (int off = 1; off < 1024; off <<= 1) {
        int v = (tid >= off) ? ssum[tid - off] : 0;
        __syncthreads();
        ssum[tid] += v;
        __syncthreads();
    }
    int prefix = (tid == 0) ? 0 : ssum[tid - 1];
    for (int i = beg; i < end; i++) {
        int c = g_cur[i];
        g_row[i] = prefix;
        g_cur[i] = prefix;
        g_inv[i] = 1.0f / (float)max(c, 1);
        prefix += c;
    }
    if (tid == 1023) g_row[N_NODES] = prefix;
}

__global__ void fill_kernel(const void* __restrict__ edges, int E) {
    int i = blockIdx.x * blockDim.x + threadIdx.x;
    if (i >= E) return;
    int s, d;
    if (g_is64) {
        const long long* p = (const long long*)edges;
        s = (int)p[i]; d = (int)p[E + i];
    } else {
        const int* p = (const int*)edges;
        s = p[i]; d = p[E + i];
    }
    int pos = atomicAdd(&g_cur[d], 1);
    g_col[pos] = s;
}

// ---------------------------------------------------------------------------
// Pre-transpose weights to k-major, concatenated K=256
// ---------------------------------------------------------------------------
__global__ void wt_kernel(const float* __restrict__ W1l,
                          const float* __restrict__ W1r,
                          const float* __restrict__ W2l,
                          const float* __restrict__ W2r) {
    int i = blockIdx.x * blockDim.x + threadIdx.x;
    if (i < 256 * 128) {
        int k = i >> 7, o = i & 127;
        g_wt1[i] = (k < 128) ? W1l[o * 128 + k] : W1r[o * 128 + (k - 128)];
    }
    if (i < 256 * 64) {
        int k = i >> 6, o = i & 63;
        g_wt2[i] = (k < 128) ? W2l[o * 128 + k] : W2r[o * 128 + (k - 128)];
    }
}

// ---------------------------------------------------------------------------
// Gather-mean aggregation: one warp per node, lane = one float4 chunk.
// Writes mean directly into g_agg (no atomics, no zeroing).
// ---------------------------------------------------------------------------
__global__ void gather_kernel(const float* __restrict__ x, int use_h) {
    int wid = (blockIdx.x * blockDim.x + threadIdx.x) >> 5;
    int lane = threadIdx.x & 31;
    if (wid >= N_NODES) return;
    const float* feat = use_h ? g_h : x;
    const float4* base = (const float4*)feat;
    int beg = g_row[wid], end = g_row[wid + 1];
    float4 acc = make_float4(0.f, 0.f, 0.f, 0.f);
    int i = beg;
    for (; i + 2 <= end; i += 2) {
        int s0 = g_col[i], s1 = g_col[i + 1];
        float4 v0 = base[(size_t)s0 * 32 + lane];
        float4 v1 = base[(size_t)s1 * 32 + lane];
        acc.x += v0.x + v1.x; acc.y += v0.y + v1.y;
        acc.z += v0.z + v1.z; acc.w += v0.w + v1.w;
    }
    if (i < end) {
        int s = g_col[i];
        float4 v = base[(size_t)s * 32 + lane];
        acc.x += v.x; acc.y += v.y; acc.z += v.z; acc.w += v.w;
    }
    float inv = g_inv[wid];
    ((float4*)g_agg)[(size_t)wid * 32 + lane] =
        make_float4(acc.x * inv, acc.y * inv, acc.z * inv, acc.w * inv);
}

// ---------------------------------------------------------------------------
// GEMM1: h = relu( [mean||x] @ Wt1 + b1l ), K=256, FFMA2 inner loop.
// Block 64 nodes x 128 outs, BK=64, 256 threads, thread = 4 nodes x 8 outs
// (two 4-out spans at o0 and 64+o0 for conflict-free weight LDS.128).
// A staged pre-duplicated as (a,a) u64 pairs.
// ---------------------------------------------------------------------------
#define G1_SMEM (64 * 65 * 8 + 64 * 128 * 4)

__global__ __launch_bounds__(256)
void gemm1_kernel(const float* __restrict__ x, const float* __restrict__ bl) {
    extern __shared__ unsigned long long sm_u[];
    unsigned long long* a2 = sm_u;              // [64][65] dup pairs
    float* w_s = (float*)(sm_u + 64 * 65);      // [64][128]

    int tid = threadIdx.x;
    int base = blockIdx.x * 64;
    int tx = tid & 15, ty = tid >> 4;
    int n0 = ty * 4, o0 = tx * 4;

    unsigned long long acc[4][4];
    {
        unsigned long long b0 = pk2(bl[o0], bl[o0 + 1]);
        unsigned long long b1 = pk2(bl[o0 + 2], bl[o0 + 3]);
        unsigned long long b2 = pk2(bl[64 + o0], bl[64 + o0 + 1]);
        unsigned long long b3 = pk2(bl[64 + o0 + 2], bl[64 + o0 + 3]);
#pragma unroll
        for (int i = 0; i < 4; i++) {
            acc[i][0] = b0; acc[i][1] = b1; acc[i][2] = b2; acc[i][3] = b3;
        }
    }

    for (int kt = 0; kt < 4; kt++) {
        const float* asrc = (kt < 2) ? g_agg : x;
        int koff = (kt & 1) * 64;
#pragma unroll
        for (int t = 0; t < 4; t++) {
            int idx = tid + t * 256;            // 0..1023
            int row = idx >> 4, c4 = idx & 15;
            int g = base + row;
            float4 v = make_float4(0.f, 0.f, 0.f, 0.f);
            if (g < N_NODES)
                v = ((const float4*)(asrc + (size_t)g * 128 + koff))[c4];
            unsigned long long* d = a2 + row * 65 + c4 * 4;
            d[0] = pk2(v.x, v.x); d[1] = pk2(v.y, v.y);
            d[2] = pk2(v.z, v.z); d[3] = pk2(v.w, v.w);
        }
        const float4* wsrc = (const float4*)(g_wt1 + kt * 64 * 128);
#pragma unroll
        for (int t = 0; t < 8; t++) {
            int idx = tid + t * 256;            // 0..2047
            ((float4*)w_s)[idx] = wsrc[idx];
        }
        __syncthreads();

        const unsigned long long* ap0 = a2 + (n0 + 0) * 65;
        const unsigned long long* ap1 = a2 + (n0 + 1) * 65;
        const unsigned long long* ap2 = a2 + (n0 + 2) * 65;
        const unsigned long long* ap3 = a2 + (n0 + 3) * 65;
#pragma unroll 4
        for (int kk = 0; kk < 64; kk++) {
            const float* wp = w_s + kk * 128;
            ulonglong2 w01 = *(const ulonglong2*)(wp + o0);
            ulonglong2 w23 = *(const ulonglong2*)(wp + 64 + o0);
            unsigned long long a0 = ap0[kk], a1 = ap1[kk];
            unsigned long long av2 = ap2[kk], a3 = ap3[kk];
            fma2(acc[0][0], a0, w01.x); fma2(acc[0][1], a0, w01.y);
            fma2(acc[0][2], a0, w23.x); fma2(acc[0][3], a0, w23.y);
            fma2(acc[1][0], a1, w01.x); fma2(acc[1][1], a1, w01.y);
            fma2(acc[1][2], a1, w23.x); fma2(acc[1][3], a1, w23.y);
            fma2(acc[2][0], av2, w01.x); fma2(acc[2][1], av2, w01.y);
            fma2(acc[2][2], av2, w23.x); fma2(acc[2][3], av2, w23.y);
            fma2(acc[3][0], a3, w01.x); fma2(acc[3][1], a3, w01.y);
            fma2(acc[3][2], a3, w23.x); fma2(acc[3][3], a3, w23.y);
        }
        __syncthreads();
    }

#pragma unroll
    for (int i = 0; i < 4; i++) {
        int g = base + n0 + i;
        if (g >= N_NODES) continue;
        float4 r0, r1;
        up2(acc[i][0], r0.x, r0.y); up2(acc[i][1], r0.z, r0.w);
        up2(acc[i][2], r1.x, r1.y); up2(acc[i][3], r1.z, r1.w);
        r0.x = fmaxf(r0.x, 0.f); r0.y = fmaxf(r0.y, 0.f);
        r0.z = fmaxf(r0.z, 0.f); r0.w = fmaxf(r0.w, 0.f);
        r1.x = fmaxf(r1.x, 0.f); r1.y = fmaxf(r1.y, 0.f);
        r1.z = fmaxf(r1.z, 0.f); r1.w = fmaxf(r1.w, 0.f);
        *(float4*)&g_h[(size_t)g * 128 + o0] = r0;
        *(float4*)&g_h[(size_t)g * 128 + 64 + o0] = r1;
    }
}

// ---------------------------------------------------------------------------
// GEMM2 + log_softmax: out = logsoftmax( [mean2||h] @ Wt2 + b2l ).
// Block 128 nodes x 64 outs, BK=64, 256 threads, thread = 4 nodes x 8 outs
// (spans o0 and 32+o0; tx = low 3 bits of lane -> shfl reduce over 8 lanes).
// ---------------------------------------------------------------------------
#define G2_SMEM (128 * 65 * 8 + 64 * 64 * 4)

__global__ __launch_bounds__(256)
void gemm2_kernel(const float* __restrict__ bl, float* __restrict__ out) {
    extern __shared__ unsigned long long sm_u[];
    unsigned long long* a2 = sm_u;              // [128][65]
    float* w_s = (float*)(sm_u + 128 * 65);     // [64][64]

    int tid = threadIdx.x;
    int base = blockIdx.x * 128;
    int tx = tid & 7, ty = tid >> 3;
    int n0 = ty * 4, o0 = tx * 4;

    unsigned long long acc[4][4];
    {
        unsigned long long b0 = pk2(bl[o0], bl[o0 + 1]);
        unsigned long long b1 = pk2(bl[o0 + 2], bl[o0 + 3]);
        unsigned long long b2 = pk2(bl[32 + o0], bl[32 + o0 + 1]);
        unsigned long long b3 = pk2(bl[32 + o0 + 2], bl[32 + o0 + 3]);
#pragma unroll
        for (int i = 0; i < 4; i++) {
            acc[i][0] = b0; acc[i][1] = b1; acc[i][2] = b2; acc[i][3] = b3;
        }
    }

    for (int kt = 0; kt < 4; kt++) {
        const float* asrc = (kt < 2) ? g_agg : g_h;
        int koff = (kt & 1) * 64;
#pragma unroll
        for (int t = 0; t < 8; t++) {
            int idx = tid + t * 256;            // 0..2047
            int row = idx >> 4, c4 = idx & 15;
            int g = base + row;
            float4 v = make_float4(0.f, 0.f, 0.f, 0.f);
            if (g < N_NODES)
                v = ((const float4*)(asrc + (size_t)g * 128 + koff))[c4];
            unsigned long long* d = a2 + row * 65 + c4 * 4;
            d[0] = pk2(v.x, v.x); d[1] = pk2(v.y, v.y);
            d[2] = pk2(v.z, v.z); d[3] = pk2(v.w, v.w);
        }
        const float4* wsrc = (const float4*)(g_wt2 + kt * 64 * 64);
#pragma unroll
        for (int t = 0; t < 4; t++) {
            int idx = tid + t * 256;            // 0..1023
            ((float4*)w_s)[idx] = wsrc[idx];
        }
        __syncthreads();

        const unsigned long long* ap0 = a2 + (n0 + 0) * 65;
        const unsigned long long* ap1 = a2 + (n0 + 1) * 65;
        const unsigned long long* ap2 = a2 + (n0 + 2) * 65;
        const unsigned long long* ap3 = a2 + (n0 + 3) * 65;
#pragma unroll 4
        for (int kk = 0; kk < 64; kk++) {
            const float* wp = w_s + kk * 64;
            ulonglong2 w01 = *(const ulonglong2*)(wp + o0);
            ulonglong2 w23 = *(const ulonglong2*)(wp + 32 + o0);
            unsigned long long a0 = ap0[kk], a1 = ap1[kk];
            unsigned long long av2 = ap2[kk], a3 = ap3[kk];
            fma2(acc[0][0], a0, w01.x); fma2(acc[0][1], a0, w01.y);
            fma2(acc[0][2], a0, w23.x); fma2(acc[0][3], a0, w23.y);
            fma2(acc[1][0], a1, w01.x); fma2(acc[1][1], a1, w01.y);
            fma2(acc[1][2], a1, w23.x); fma2(acc[1][3], a1, w23.y);
            fma2(acc[2][0], av2, w01.x); fma2(acc[2][1], av2, w01.y);
            fma2(acc[2][2], av2, w23.x); fma2(acc[2][3], av2, w23.y);
            fma2(acc[3][0], a3, w01.x); fma2(acc[3][1], a3, w01.y);
            fma2(acc[3][2], a3, w23.x); fma2(acc[3][3], a3, w23.y);
        }
        __syncthreads();
    }

    // Fused log_softmax: reductions across the 8 tx-lanes (low 3 lane bits).
    // Shuffles run unconditionally; only stores are guarded.
#pragma unroll
    for (int i = 0; i < 4; i++) {
        int g = base + n0 + i;
        float v[8];
        up2(acc[i][0], v[0], v[1]); up2(acc[i][1], v[2], v[3]);
        up2(acc[i][2], v[4], v[5]); up2(acc[i][3], v[6], v[7]);
        float m = v[0];
#pragma unroll
        for (int j = 1; j < 8; j++) m = fmaxf(m, v[j]);
#pragma unroll
        for (int off = 1; off < 8; off <<= 1)
            m = fmaxf(m, __shfl_xor_sync(0xffffffffu, m, off));
        float s = 0.f;
#pragma unroll
        for (int j = 0; j < 8; j++) s += expf(v[j] - m);
#pragma unroll
        for (int off = 1; off < 8; off <<= 1)
            s += __shfl_xor_sync(0xffffffffu, s, off);
        float lse = m + logf(s);
        if (g < N_NODES) {
            float4 r0 = make_float4(v[0] - lse, v[1] - lse, v[2] - lse, v[3] - lse);
            float4 r1 = make_float4(v[4] - lse, v[5] - lse, v[6] - lse, v[7] - lse);
            *(float4*)&out[(size_t)g * 64 + o0] = r0;
            *(float4*)&out[(size_t)g * 64 + 32 + o0] = r1;
        }
    }
}

// ---------------------------------------------------------------------------
// Launch
// ---------------------------------------------------------------------------
extern "C" void kernel_launch(void* const* d_in, const int* in_sizes, int n_in,
                              void* d_out, int out_size) {
    const float* x   = (const float*)d_in[0];
    const void*  edg = d_in[1];
    const float* W1l = (const float*)d_in[2];
    const float* b1l = (const float*)d_in[3];
    const float* W1r = (const float*)d_in[4];
    const float* W2l = (const float*)d_in[5];
    const float* b2l = (const float*)d_in[6];
    const float* W2r = (const float*)d_in[7];
    float* out = (float*)d_out;

    int E = in_sizes[1] / 2;
    if (E > E_MAX) E = E_MAX;

    cudaFuncSetAttribute(gemm1_kernel,
                         cudaFuncAttributeMaxDynamicSharedMemorySize, G1_SMEM);
    cudaFuncSetAttribute(gemm2_kernel,
                         cudaFuncAttributeMaxDynamicSharedMemorySize, G2_SMEM);

    int eb = (E + 255) / 256;
    int gather_blocks = (N_NODES * 32 + 255) / 256;   // 12500
    int g1_blocks = (N_NODES + 63) / 64;              // 1563
    int g2_blocks = (N_NODES + 127) / 128;            // 782

    detect_kernel<<<1, 256>>>((const unsigned int*)edg);
    zero_cur_kernel<<<(N_NODES + 255) / 256, 256>>>();
    hist_kernel<<<eb, 256>>>(edg, E);
    scan_kernel<<<1, 1024>>>();
    fill_kernel<<<eb, 256>>>(edg, E);
    wt_kernel<<<128, 256>>>(W1l, W1r, W2l, W2r);

    gather_kernel<<<gather_blocks, 256>>>(x, 0);
    gemm1_kernel<<<g1_blocks, 256, G1_SMEM>>>(x, b1l);
    gather_kernel<<<gather_blocks, 256>>>(x, 1);
    gemm2_kernel<<<g2_blocks, 256, G2_SMEM>>>(b2l, out);
}

// round 5
// speedup vs baseline: 3.9223x; 1.4125x over previous
#include <cuda_runtime.h>
#include <math.h>

#define N_NODES 100000
#define E_MAX   1600000
#define NBLK_SCAN 98   // ceil(N_NODES / 1024)

// ---------------------------------------------------------------------------
// Scratch (__device__ globals: allocation-free rule)
// ---------------------------------------------------------------------------
__device__ __align__(16) float g_agg[(size_t)N_NODES * 128]; // mean features
__device__ __align__(16) float g_h[(size_t)N_NODES * 128];   // layer-1 output
__device__ int   g_row[N_NODES + 1];   // CSR row_ptr (by dst)
__device__ int   g_cur[N_NODES];       // counts, then fill cursor
__device__ int   g_col[E_MAX];         // CSR col (src ids)
__device__ float g_inv[N_NODES];       // 1/max(deg,1)
__device__ int   g_bsum[NBLK_SCAN];    // per-block sums for scan
__device__ int   g_boff[NBLK_SCAN];    // per-block exclusive offsets
__device__ __align__(16) float g_wt1[256 * 128]; // k-major [k][o]: W1l||W1r
__device__ __align__(16) float g_wt2[256 * 64];  // k-major [k][o]: W2l||W2r
__device__ int   g_is64;

// ---------------------------------------------------------------------------
// Packed f32x2 helpers (Blackwell FFMA2 — PTX-only)
// ---------------------------------------------------------------------------
__device__ __forceinline__ void fma2(unsigned long long& d,
                                     unsigned long long a,
                                     unsigned long long b) {
    asm("fma.rn.f32x2 %0, %1, %2, %0;" : "+l"(d) : "l"(a), "l"(b));
}
__device__ __forceinline__ unsigned long long pk2(float x, float y) {
    unsigned long long r;
    asm("mov.b64 %0, {%1, %2};" : "=l"(r) : "f"(x), "f"(y));
    return r;
}
__device__ __forceinline__ void up2(unsigned long long v, float& x, float& y) {
    asm("mov.b64 {%0, %1}, %2;" : "=f"(x), "=f"(y) : "l"(v));
}

// ---------------------------------------------------------------------------
// int64 vs int32 edge dtype detection (odd 32-bit words all zero => int64)
// ---------------------------------------------------------------------------
__global__ void detect_kernel(const unsigned int* __restrict__ e) {
    __shared__ int nz;
    if (threadIdx.x == 0) nz = 0;
    __syncthreads();
    unsigned int acc = 0;
    for (int i = threadIdx.x; i < 1024; i += blockDim.x)
        acc |= e[2 * i + 1];
    if (acc) atomicOr(&nz, 1);
    __syncthreads();
    if (threadIdx.x == 0) g_is64 = (nz == 0) ? 1 : 0;
}

__global__ void zero_cur_kernel() {
    int i = blockIdx.x * blockDim.x + threadIdx.x;
    if (i < N_NODES) g_cur[i] = 0;
}

// ---------------------------------------------------------------------------
// CSR build: histogram -> 3-phase full-chip scan -> fill
// ---------------------------------------------------------------------------
__global__ void hist_kernel(const void* __restrict__ edges, int E) {
    int i = blockIdx.x * blockDim.x + threadIdx.x;
    if (i >= E) return;
    int d = g_is64 ? (int)((const long long*)edges)[E + i]
                   : ((const int*)edges)[E + i];
    atomicAdd(&g_cur[d], 1);
}

// Phase 1: per-block sums (98 blocks x 1024 threads, coalesced)
__global__ void scan_sum_kernel() {
    __shared__ int wsum[32];
    int tid = threadIdx.x;
    int i = blockIdx.x * 1024 + tid;
    int c = (i < N_NODES) ? g_cur[i] : 0;
    int v = c;
#pragma unroll
    for (int off = 16; off; off >>= 1) v += __shfl_xor_sync(~0u, v, off);
    if ((tid & 31) == 0) wsum[tid >> 5] = v;
    __syncthreads();
    if (tid < 32) {
        int s = wsum[tid];
#pragma unroll
        for (int off = 16; off; off >>= 1) s += __shfl_xor_sync(~0u, s, off);
        if (tid == 0) g_bsum[blockIdx.x] = s;
    }
}

// Phase 2: scan the 98 block sums (single 128-thread block)
__global__ void scan_offsets_kernel() {
    __shared__ int wsum[4];
    int tid = threadIdx.x;
    int lane = tid & 31, w = tid >> 5;
    int v = (tid < NBLK_SCAN) ? g_bsum[tid] : 0;
    int inc = v;
#pragma unroll
    for (int off = 1; off < 32; off <<= 1) {
        int t = __shfl_up_sync(~0u, inc, off);
        if (lane >= off) inc += t;
    }
    if (lane == 31) wsum[w] = inc;
    __syncthreads();
    int woff = 0;
    for (int j = 0; j < w; j++) woff += wsum[j];
    int excl = woff + inc - v;
    if (tid < NBLK_SCAN) g_boff[tid] = excl;
    if (tid == NBLK_SCAN - 1) g_row[N_NODES] = excl + v;
}

// Phase 3: block-local exclusive scan + offset; write row/cursor/inv
__global__ void scan_write_kernel() {
    __shared__ int wsum[32];
    int tid = threadIdx.x;
    int lane = tid & 31, w = tid >> 5;
    int i = blockIdx.x * 1024 + tid;
    int c = (i < N_NODES) ? g_cur[i] : 0;
    int inc = c;
#pragma unroll
    for (int off = 1; off < 32; off <<= 1) {
        int t = __shfl_up_sync(~0u, inc, off);
        if (lane >= off) inc += t;
    }
    if (lane == 31) wsum[w] = inc;
    __syncthreads();
    if (tid < 32) {
        int v = wsum[tid];
        int winc = v;
#pragma unroll
        for (int off = 1; off < 32; off <<= 1) {
            int t = __shfl_up_sync(~0u, winc, off);
            if (tid >= off) winc += t;
        }
        wsum[tid] = winc - v;   // exclusive warp offset
    }
    __syncthreads();
    int excl = g_boff[blockIdx.x] + wsum[w] + inc - c;
    if (i < N_NODES) {
        g_row[i] = excl;
        g_cur[i] = excl;
        g_inv[i] = 1.0f / (float)max(c, 1);
    }
}

__global__ void fill_kernel(const void* __restrict__ edges, int E) {
    int i = blockIdx.x * blockDim.x + threadIdx.x;
    if (i >= E) return;
    int s, d;
    if (g_is64) {
        const long long* p = (const long long*)edges;
        s = (int)p[i]; d = (int)p[E + i];
    } else {
        const int* p = (const int*)edges;
        s = p[i]; d = p[E + i];
    }
    int pos = atomicAdd(&g_cur[d], 1);
    g_col[pos] = s;
}

// ---------------------------------------------------------------------------
// Pre-transpose weights to k-major, concatenated K=256
// ---------------------------------------------------------------------------
__global__ void wt_kernel(const float* __restrict__ W1l,
                          const float* __restrict__ W1r,
                          const float* __restrict__ W2l,
                          const float* __restrict__ W2r) {
    int i = blockIdx.x * blockDim.x + threadIdx.x;
    if (i < 256 * 128) {
        int k = i >> 7, o = i & 127;
        g_wt1[i] = (k < 128) ? W1l[o * 128 + k] : W1r[o * 128 + (k - 128)];
    }
    if (i < 256 * 64) {
        int k = i >> 6, o = i & 63;
        g_wt2[i] = (k < 128) ? W2l[o * 128 + k] : W2r[o * 128 + (k - 128)];
    }
}

// ---------------------------------------------------------------------------
// Gather-mean aggregation: one warp per node, lane = one float4 chunk.
// ---------------------------------------------------------------------------
__global__ void gather_kernel(const float* __restrict__ x, int use_h) {
    int wid = (blockIdx.x * blockDim.x + threadIdx.x) >> 5;
    int lane = threadIdx.x & 31;
    if (wid >= N_NODES) return;
    const float* feat = use_h ? g_h : x;
    const float4* base = (const float4*)feat;
    int beg = g_row[wid], end = g_row[wid + 1];
    float4 acc = make_float4(0.f, 0.f, 0.f, 0.f);
    int i = beg;
    for (; i + 2 <= end; i += 2) {
        int s0 = g_col[i], s1 = g_col[i + 1];
        float4 v0 = base[(size_t)s0 * 32 + lane];
        float4 v1 = base[(size_t)s1 * 32 + lane];
        acc.x += v0.x + v1.x; acc.y += v0.y + v1.y;
        acc.z += v0.z + v1.z; acc.w += v0.w + v1.w;
    }
    if (i < end) {
        int s = g_col[i];
        float4 v = base[(size_t)s * 32 + lane];
        acc.x += v.x; acc.y += v.y; acc.z += v.z; acc.w += v.w;
    }
    float inv = g_inv[wid];
    ((float4*)g_agg)[(size_t)wid * 32 + lane] =
        make_float4(acc.x * inv, acc.y * inv, acc.z * inv, acc.w * inv);
}

// ---------------------------------------------------------------------------
// GEMM1: h = relu( [mean||x] @ Wt1 + b1l ), K=256, FFMA2 inner loop.
// ---------------------------------------------------------------------------
#define G1_SMEM (64 * 65 * 8 + 64 * 128 * 4)

__global__ __launch_bounds__(256)
void gemm1_kernel(const float* __restrict__ x, const float* __restrict__ bl) {
    extern __shared__ unsigned long long sm_u[];
    unsigned long long* a2 = sm_u;              // [64][65] dup pairs
    float* w_s = (float*)(sm_u + 64 * 65);      // [64][128]

    int tid = threadIdx.x;
    int base = blockIdx.x * 64;
    int tx = tid & 15, ty = tid >> 4;
    int n0 = ty * 4, o0 = tx * 4;

    unsigned long long acc[4][4];
    {
        unsigned long long b0 = pk2(bl[o0], bl[o0 + 1]);
        unsigned long long b1 = pk2(bl[o0 + 2], bl[o0 + 3]);
        unsigned long long b2 = pk2(bl[64 + o0], bl[64 + o0 + 1]);
        unsigned long long b3 = pk2(bl[64 + o0 + 2], bl[64 + o0 + 3]);
#pragma unroll
        for (int i = 0; i < 4; i++) {
            acc[i][0] = b0; acc[i][1] = b1; acc[i][2] = b2; acc[i][3] = b3;
        }
    }

    for (int kt = 0; kt < 4; kt++) {
        const float* asrc = (kt < 2) ? g_agg : x;
        int koff = (kt & 1) * 64;
#pragma unroll
        for (int t = 0; t < 4; t++) {
            int idx = tid + t * 256;            // 0..1023
            int row = idx >> 4, c4 = idx & 15;
            int g = base + row;
            float4 v = make_float4(0.f, 0.f, 0.f, 0.f);
            if (g < N_NODES)
                v = ((const float4*)(asrc + (size_t)g * 128 + koff))[c4];
            unsigned long long* d = a2 + row * 65 + c4 * 4;
            d[0] = pk2(v.x, v.x); d[1] = pk2(v.y, v.y);
            d[2] = pk2(v.z, v.z); d[3] = pk2(v.w, v.w);
        }
        const float4* wsrc = (const float4*)(g_wt1 + kt * 64 * 128);
#pragma unroll
        for (int t = 0; t < 8; t++) {
            int idx = tid + t * 256;            // 0..2047
            ((float4*)w_s)[idx] = wsrc[idx];
        }
        __syncthreads();

        const unsigned long long* ap0 = a2 + (n0 + 0) * 65;
        const unsigned long long* ap1 = a2 + (n0 + 1) * 65;
        const unsigned long long* ap2 = a2 + (n0 + 2) * 65;
        const unsigned long long* ap3 = a2 + (n0 + 3) * 65;
#pragma unroll 4
        for (int kk = 0; kk < 64; kk++) {
            const float* wp = w_s + kk * 128;
            ulonglong2 w01 = *(const ulonglong2*)(wp + o0);
            ulonglong2 w23 = *(const ulonglong2*)(wp + 64 + o0);
            unsigned long long a0 = ap0[kk], a1 = ap1[kk];
            unsigned long long av2 = ap2[kk], a3 = ap3[kk];
            fma2(acc[0][0], a0, w01.x); fma2(acc[0][1], a0, w01.y);
            fma2(acc[0][2], a0, w23.x); fma2(acc[0][3], a0, w23.y);
            fma2(acc[1][0], a1, w01.x); fma2(acc[1][1], a1, w01.y);
            fma2(acc[1][2], a1, w23.x); fma2(acc[1][3], a1, w23.y);
            fma2(acc[2][0], av2, w01.x); fma2(acc[2][1], av2, w01.y);
            fma2(acc[2][2], av2, w23.x); fma2(acc[2][3], av2, w23.y);
            fma2(acc[3][0], a3, w01.x); fma2(acc[3][1], a3, w01.y);
            fma2(acc[3][2], a3, w23.x); fma2(acc[3][3], a3, w23.y);
        }
        __syncthreads();
    }

#pragma unroll
    for (int i = 0; i < 4; i++) {
        int g = base + n0 + i;
        if (g >= N_NODES) continue;
        float4 r0, r1;
        up2(acc[i][0], r0.x, r0.y); up2(acc[i][1], r0.z, r0.w);
        up2(acc[i][2], r1.x, r1.y); up2(acc[i][3], r1.z, r1.w);
        r0.x = fmaxf(r0.x, 0.f); r0.y = fmaxf(r0.y, 0.f);
        r0.z = fmaxf(r0.z, 0.f); r0.w = fmaxf(r0.w, 0.f);
        r1.x = fmaxf(r1.x, 0.f); r1.y = fmaxf(r1.y, 0.f);
        r1.z = fmaxf(r1.z, 0.f); r1.w = fmaxf(r1.w, 0.f);
        *(float4*)&g_h[(size_t)g * 128 + o0] = r0;
        *(float4*)&g_h[(size_t)g * 128 + 64 + o0] = r1;
    }
}

// ---------------------------------------------------------------------------
// GEMM2 + log_softmax
// ---------------------------------------------------------------------------
#define G2_SMEM (128 * 65 * 8 + 64 * 64 * 4)

__global__ __launch_bounds__(256)
void gemm2_kernel(const float* __restrict__ bl, float* __restrict__ out) {
    extern __shared__ unsigned long long sm_u[];
    unsigned long long* a2 = sm_u;              // [128][65]
    float* w_s = (float*)(sm_u + 128 * 65);     // [64][64]

    int tid = threadIdx.x;
    int base = blockIdx.x * 128;
    int tx = tid & 7, ty = tid >> 3;
    int n0 = ty * 4, o0 = tx * 4;

    unsigned long long acc[4][4];
    {
        unsigned long long b0 = pk2(bl[o0], bl[o0 + 1]);
        unsigned long long b1 = pk2(bl[o0 + 2], bl[o0 + 3]);
        unsigned long long b2 = pk2(bl[32 + o0], bl[32 + o0 + 1]);
        unsigned long long b3 = pk2(bl[32 + o0 + 2], bl[32 + o0 + 3]);
#pragma unroll
        for (int i = 0; i < 4; i++) {
            acc[i][0] = b0; acc[i][1] = b1; acc[i][2] = b2; acc[i][3] = b3;
        }
    }

    for (int kt = 0; kt < 4; kt++) {
        const float* asrc = (kt < 2) ? g_agg : g_h;
        int koff = (kt & 1) * 64;
#pragma unroll
        for (int t = 0; t < 8; t++) {
            int idx = tid + t * 256;            // 0..2047
            int row = idx >> 4, c4 = idx & 15;
            int g = base + row;
            float4 v = make_float4(0.f, 0.f, 0.f, 0.f);
            if (g < N_NODES)
                v = ((const float4*)(asrc + (size_t)g * 128 + koff))[c4];
            unsigned long long* d = a2 + row * 65 + c4 * 4;
            d[0] = pk2(v.x, v.x); d[1] = pk2(v.y, v.y);
            d[2] = pk2(v.z, v.z); d[3] = pk2(v.w, v.w);
        }
        const float4* wsrc = (const float4*)(g_wt2 + kt * 64 * 64);
#pragma unroll
        for (int t = 0; t < 4; t++) {
            int idx = tid + t * 256;            // 0..1023
            ((float4*)w_s)[idx] = wsrc[idx];
        }
        __syncthreads();

        const unsigned long long* ap0 = a2 + (n0 + 0) * 65;
        const unsigned long long* ap1 = a2 + (n0 + 1) * 65;
        const unsigned long long* ap2 = a2 + (n0 + 2) * 65;
        const unsigned long long* ap3 = a2 + (n0 + 3) * 65;
#pragma unroll 4
        for (int kk = 0; kk < 64; kk++) {
            const float* wp = w_s + kk * 64;
            ulonglong2 w01 = *(const ulonglong2*)(wp + o0);
            ulonglong2 w23 = *(const ulonglong2*)(wp + 32 + o0);
            unsigned long long a0 = ap0[kk], a1 = ap1[kk];
            unsigned long long av2 = ap2[kk], a3 = ap3[kk];
            fma2(acc[0][0], a0, w01.x); fma2(acc[0][1], a0, w01.y);
            fma2(acc[0][2], a0, w23.x); fma2(acc[0][3], a0, w23.y);
            fma2(acc[1][0], a1, w01.x); fma2(acc[1][1], a1, w01.y);
            fma2(acc[1][2], a1, w23.x); fma2(acc[1][3], a1, w23.y);
            fma2(acc[2][0], av2, w01.x); fma2(acc[2][1], av2, w01.y);
            fma2(acc[2][2], av2, w23.x); fma2(acc[2][3], av2, w23.y);
            fma2(acc[3][0], a3, w01.x); fma2(acc[3][1], a3, w01.y);
            fma2(acc[3][2], a3, w23.x); fma2(acc[3][3], a3, w23.y);
        }
        __syncthreads();
    }

#pragma unroll
    for (int i = 0; i < 4; i++) {
        int g = base + n0 + i;
        float v[8];
        up2(acc[i][0], v[0], v[1]); up2(acc[i][1], v[2], v[3]);
        up2(acc[i][2], v[4], v[5]); up2(acc[i][3], v[6], v[7]);
        float m = v[0];
#pragma unroll
        for (int j = 1; j < 8; j++) m = fmaxf(m, v[j]);
#pragma unroll
        for (int off = 1; off < 8; off <<= 1)
            m = fmaxf(m, __shfl_xor_sync(0xffffffffu, m, off));
        float s = 0.f;
#pragma unroll
        for (int j = 0; j < 8; j++) s += expf(v[j] - m);
#pragma unroll
        for (int off = 1; off < 8; off <<= 1)
            s += __shfl_xor_sync(0xffffffffu, s, off);
        float lse = m + logf(s);
        if (g < N_NODES) {
            float4 r0 = make_float4(v[0] - lse, v[1] - lse, v[2] - lse, v[3] - lse);
            float4 r1 = make_float4(v[4] - lse, v[5] - lse, v[6] - lse, v[7] - lse);
            *(float4*)&out[(size_t)g * 64 + o0] = r0;
            *(float4*)&out[(size_t)g * 64 + 32 + o0] = r1;
        }
    }
}

// ---------------------------------------------------------------------------
// Launch
// ---------------------------------------------------------------------------
extern "C" void kernel_launch(void* const* d_in, const int* in_sizes, int n_in,
                              void* d_out, int out_size) {
    const float* x   = (const float*)d_in[0];
    const void*  edg = d_in[1];
    const float* W1l = (const float*)d_in[2];
    const float* b1l = (const float*)d_in[3];
    const float* W1r = (const float*)d_in[4];
    const float* W2l = (const float*)d_in[5];
    const float* b2l = (const float*)d_in[6];
    const float* W2r = (const float*)d_in[7];
    float* out = (float*)d_out;

    int E = in_sizes[1] / 2;
    if (E > E_MAX) E = E_MAX;

    cudaFuncSetAttribute(gemm1_kernel,
                         cudaFuncAttributeMaxDynamicSharedMemorySize, G1_SMEM);
    cudaFuncSetAttribute(gemm2_kernel,
                         cudaFuncAttributeMaxDynamicSharedMemorySize, G2_SMEM);

    int eb = (E + 255) / 256;
    int gather_blocks = (N_NODES * 32 + 255) / 256;   // 12500
    int g1_blocks = (N_NODES + 63) / 64;              // 1563
    int g2_blocks = (N_NODES + 127) / 128;            // 782

    detect_kernel<<<1, 256>>>((const unsigned int*)edg);
    zero_cur_kernel<<<(N_NODES + 255) / 256, 256>>>();
    hist_kernel<<<eb, 256>>>(edg, E);
    scan_sum_kernel<<<NBLK_SCAN, 1024>>>();
    scan_offsets_kernel<<<1, 128>>>();
    scan_write_kernel<<<NBLK_SCAN, 1024>>>();
    fill_kernel<<<eb, 256>>>(edg, E);
    wt_kernel<<<128, 256>>>(W1l, W1r, W2l, W2r);

    gather_kernel<<<gather_blocks, 256>>>(x, 0);
    gemm1_kernel<<<g1_blocks, 256, G1_SMEM>>>(x, b1l);
    gather_kernel<<<gather_blocks, 256>>>(x, 1);
    gemm2_kernel<<<g2_blocks, 256, G2_SMEM>>>(b2l, out);
}

// round 6
// speedup vs baseline: 4.0655x; 1.0365x over previous
#include <cuda_runtime.h>
#include <math.h>

#define N_NODES 100000
#define E_MAX   1600000
#define NBLK_SCAN 98   // ceil(N_NODES / 1024)

// ---------------------------------------------------------------------------
// Scratch (__device__ globals: allocation-free rule)
// ---------------------------------------------------------------------------
__device__ __align__(16) float g_agg[(size_t)N_NODES * 128]; // layer-1 mean
__device__ __align__(16) float g_h[(size_t)N_NODES * 128];   // layer-1 output
__device__ __align__(16) float g_y[(size_t)N_NODES * 64];    // h @ W2l^T
__device__ __align__(16) float g_aggy[(size_t)N_NODES * 64]; // mean_agg(y)
__device__ int   g_row[N_NODES + 1];   // CSR row_ptr (by dst)
__device__ int   g_cur[N_NODES];       // counts, then fill cursor
__device__ int   g_col[E_MAX];         // CSR col (src ids)
__device__ float g_inv[N_NODES];       // 1/max(deg,1)
__device__ int   g_bsum[NBLK_SCAN];    // per-block sums for scan
__device__ int   g_boff[NBLK_SCAN];    // per-block exclusive offsets
__device__ __align__(16) float g_wt1[256 * 128]; // k-major [k][o]: W1l||W1r
__device__ __align__(16) float g_wt2[256 * 64];  // k-major [k][o]: W2l||W2r
__device__ int   g_is64;

// ---------------------------------------------------------------------------
// Packed f32x2 helpers (Blackwell FFMA2 — PTX-only)
// ---------------------------------------------------------------------------
__device__ __forceinline__ void fma2(unsigned long long& d,
                                     unsigned long long a,
                                     unsigned long long b) {
    asm("fma.rn.f32x2 %0, %1, %2, %0;" : "+l"(d) : "l"(a), "l"(b));
}
__device__ __forceinline__ unsigned long long pk2(float x, float y) {
    unsigned long long r;
    asm("mov.b64 %0, {%1, %2};" : "=l"(r) : "f"(x), "f"(y));
    return r;
}
__device__ __forceinline__ void up2(unsigned long long v, float& x, float& y) {
    asm("mov.b64 {%0, %1}, %2;" : "=f"(x), "=f"(y) : "l"(v));
}

// ---------------------------------------------------------------------------
// Setup: block 0 detects int64 vs int32 edges; all blocks zero g_cur.
// ---------------------------------------------------------------------------
__global__ void setup_kernel(const unsigned int* __restrict__ e) {
    int i = blockIdx.x * blockDim.x + threadIdx.x;
    if (i < N_NODES) g_cur[i] = 0;
    if (blockIdx.x == 0) {
        __shared__ int nz;
        if (threadIdx.x == 0) nz = 0;
        __syncthreads();
        unsigned int acc = 0;
        for (int j = threadIdx.x; j < 1024; j += blockDim.x)
            acc |= e[2 * j + 1];
        if (acc) atomicOr(&nz, 1);
        __syncthreads();
        if (threadIdx.x == 0) g_is64 = (nz == 0) ? 1 : 0;
    }
}

// ---------------------------------------------------------------------------
// CSR build: histogram -> 3-phase full-chip scan -> fill
// ---------------------------------------------------------------------------
__global__ void hist_kernel(const void* __restrict__ edges, int E) {
    int i = blockIdx.x * blockDim.x + threadIdx.x;
    if (i >= E) return;
    int d = g_is64 ? (int)((const long long*)edges)[E + i]
                   : ((const int*)edges)[E + i];
    atomicAdd(&g_cur[d], 1);
}

// Phase 1: per-block sums; also folds the weight transpose (independent work).
__global__ void scan_sum_kernel(const float* __restrict__ W1l,
                                const float* __restrict__ W1r,
                                const float* __restrict__ W2l,
                                const float* __restrict__ W2r) {
    __shared__ int wsum[32];
    int tid = threadIdx.x;
    int i = blockIdx.x * 1024 + tid;
    int c = (i < N_NODES) ? g_cur[i] : 0;
    int v = c;
#pragma unroll
    for (int off = 16; off; off >>= 1) v += __shfl_xor_sync(~0u, v, off);
    if ((tid & 31) == 0) wsum[tid >> 5] = v;

    // Weight transpose: 32768 + 16384 elements over 98*1024 threads
    if (i < 256 * 128) {
        int k = i >> 7, o = i & 127;
        g_wt1[i] = (k < 128) ? W1l[o * 128 + k] : W1r[o * 128 + (k - 128)];
    }
    {
        int j = i - 256 * 128;
        if (j >= 0 && j < 256 * 64) {
            int k = j >> 6, o = j & 63;
            g_wt2[j] = (k < 128) ? W2l[o * 128 + k] : W2r[o * 128 + (k - 128)];
        }
    }

    __syncthreads();
    if (tid < 32) {
        int s = wsum[tid];
#pragma unroll
        for (int off = 16; off; off >>= 1) s += __shfl_xor_sync(~0u, s, off);
        if (tid == 0) g_bsum[blockIdx.x] = s;
    }
}

// Phase 2: scan the 98 block sums (single 128-thread block)
__global__ void scan_offsets_kernel() {
    __shared__ int wsum[4];
    int tid = threadIdx.x;
    int lane = tid & 31, w = tid >> 5;
    int v = (tid < NBLK_SCAN) ? g_bsum[tid] : 0;
    int inc = v;
#pragma unroll
    for (int off = 1; off < 32; off <<= 1) {
        int t = __shfl_up_sync(~0u, inc, off);
        if (lane >= off) inc += t;
    }
    if (lane == 31) wsum[w] = inc;
    __syncthreads();
    int woff = 0;
    for (int j = 0; j < w; j++) woff += wsum[j];
    int excl = woff + inc - v;
    if (tid < NBLK_SCAN) g_boff[tid] = excl;
    if (tid == NBLK_SCAN - 1) g_row[N_NODES] = excl + v;
}

// Phase 3: block-local exclusive scan + offset; write row/cursor/inv
__global__ void scan_write_kernel() {
    __shared__ int wsum[32];
    int tid = threadIdx.x;
    int lane = tid & 31, w = tid >> 5;
    int i = blockIdx.x * 1024 + tid;
    int c = (i < N_NODES) ? g_cur[i] : 0;
    int inc = c;
#pragma unroll
    for (int off = 1; off < 32; off <<= 1) {
        int t = __shfl_up_sync(~0u, inc, off);
        if (lane >= off) inc += t;
    }
    if (lane == 31) wsum[w] = inc;
    __syncthreads();
    if (tid < 32) {
        int v = wsum[tid];
        int winc = v;
#pragma unroll
        for (int off = 1; off < 32; off <<= 1) {
            int t = __shfl_up_sync(~0u, winc, off);
            if (tid >= off) winc += t;
        }
        wsum[tid] = winc - v;   // exclusive warp offset
    }
    __syncthreads();
    int excl = g_boff[blockIdx.x] + wsum[w] + inc - c;
    if (i < N_NODES) {
        g_row[i] = excl;
        g_cur[i] = excl;
        g_inv[i] = 1.0f / (float)max(c, 1);
    }
}

__global__ void fill_kernel(const void* __restrict__ edges, int E) {
    int i = blockIdx.x * blockDim.x + threadIdx.x;
    if (i >= E) return;
    int s, d;
    if (g_is64) {
        const long long* p = (const long long*)edges;
        s = (int)p[i]; d = (int)p[E + i];
    } else {
        const int* p = (const int*)edges;
        s = p[i]; d = p[E + i];
    }
    int pos = atomicAdd(&g_cur[d], 1);
    g_col[pos] = s;
}

// ---------------------------------------------------------------------------
// Gather-mean (128-wide): one warp per node, lane = one float4 chunk.
// ---------------------------------------------------------------------------
__global__ void gather128_kernel(const float* __restrict__ x) {
    int wid = (blockIdx.x * blockDim.x + threadIdx.x) >> 5;
    int lane = threadIdx.x & 31;
    if (wid >= N_NODES) return;
    const float4* base = (const float4*)x;
    int beg = g_row[wid], end = g_row[wid + 1];
    float4 acc = make_float4(0.f, 0.f, 0.f, 0.f);
    int i = beg;
    for (; i + 2 <= end; i += 2) {
        int s0 = g_col[i], s1 = g_col[i + 1];
        float4 v0 = base[(size_t)s0 * 32 + lane];
        float4 v1 = base[(size_t)s1 * 32 + lane];
        acc.x += v0.x + v1.x; acc.y += v0.y + v1.y;
        acc.z += v0.z + v1.z; acc.w += v0.w + v1.w;
    }
    if (i < end) {
        int s = g_col[i];
        float4 v = base[(size_t)s * 32 + lane];
        acc.x += v.x; acc.y += v.y; acc.z += v.z; acc.w += v.w;
    }
    float inv = g_inv[wid];
    ((float4*)g_agg)[(size_t)wid * 32 + lane] =
        make_float4(acc.x * inv, acc.y * inv, acc.z * inv, acc.w * inv);
}

// ---------------------------------------------------------------------------
// Gather-mean (64-wide, over g_y): half-warp (16 lanes) per node.
// ---------------------------------------------------------------------------
__global__ void gather64_kernel() {
    int nid = (blockIdx.x * blockDim.x + threadIdx.x) >> 4;
    int lane = threadIdx.x & 15;
    if (nid >= N_NODES) return;
    const float4* base = (const float4*)g_y;
    int beg = g_row[nid], end = g_row[nid + 1];
    float4 acc = make_float4(0.f, 0.f, 0.f, 0.f);
    int i = beg;
    for (; i + 2 <= end; i += 2) {
        int s0 = g_col[i], s1 = g_col[i + 1];
        float4 v0 = base[(size_t)s0 * 16 + lane];
        float4 v1 = base[(size_t)s1 * 16 + lane];
        acc.x += v0.x + v1.x; acc.y += v0.y + v1.y;
        acc.z += v0.z + v1.z; acc.w += v0.w + v1.w;
    }
    if (i < end) {
        int s = g_col[i];
        float4 v = base[(size_t)s * 16 + lane];
        acc.x += v.x; acc.y += v.y; acc.z += v.z; acc.w += v.w;
    }
    float inv = g_inv[nid];
    ((float4*)g_aggy)[(size_t)nid * 16 + lane] =
        make_float4(acc.x * inv, acc.y * inv, acc.z * inv, acc.w * inv);
}

// ---------------------------------------------------------------------------
// GEMM1: h = relu( [mean||x] @ Wt1 + b1l ), K=256, FFMA2 inner loop.
// Block 64 nodes x 128 outs, BK=64, 256 threads, thread = 4 nodes x 8 outs.
// ---------------------------------------------------------------------------
#define G1_SMEM (64 * 65 * 8 + 64 * 128 * 4)

__global__ __launch_bounds__(256)
void gemm1_kernel(const float* __restrict__ x, const float* __restrict__ bl) {
    extern __shared__ unsigned long long sm_u[];
    unsigned long long* a2 = sm_u;              // [64][65] dup pairs
    float* w_s = (float*)(sm_u + 64 * 65);      // [64][128]

    int tid = threadIdx.x;
    int base = blockIdx.x * 64;
    int tx = tid & 15, ty = tid >> 4;
    int n0 = ty * 4, o0 = tx * 4;

    unsigned long long acc[4][4];
    {
        unsigned long long b0 = pk2(bl[o0], bl[o0 + 1]);
        unsigned long long b1 = pk2(bl[o0 + 2], bl[o0 + 3]);
        unsigned long long b2 = pk2(bl[64 + o0], bl[64 + o0 + 1]);
        unsigned long long b3 = pk2(bl[64 + o0 + 2], bl[64 + o0 + 3]);
#pragma unroll
        for (int i = 0; i < 4; i++) {
            acc[i][0] = b0; acc[i][1] = b1; acc[i][2] = b2; acc[i][3] = b3;
        }
    }

    for (int kt = 0; kt < 4; kt++) {
        const float* asrc = (kt < 2) ? g_agg : x;
        int koff = (kt & 1) * 64;
#pragma unroll
        for (int t = 0; t < 4; t++) {
            int idx = tid + t * 256;            // 0..1023
            int row = idx >> 4, c4 = idx & 15;
            int g = base + row;
            float4 v = make_float4(0.f, 0.f, 0.f, 0.f);
            if (g < N_NODES)
                v = ((const float4*)(asrc + (size_t)g * 128 + koff))[c4];
            unsigned long long* d = a2 + row * 65 + c4 * 4;
            d[0] = pk2(v.x, v.x); d[1] = pk2(v.y, v.y);
            d[2] = pk2(v.z, v.z); d[3] = pk2(v.w, v.w);
        }
        const float4* wsrc = (const float4*)(g_wt1 + kt * 64 * 128);
#pragma unroll
        for (int t = 0; t < 8; t++) {
            int idx = tid + t * 256;            // 0..2047
            ((float4*)w_s)[idx] = wsrc[idx];
        }
        __syncthreads();

        const unsigned long long* ap0 = a2 + (n0 + 0) * 65;
        const unsigned long long* ap1 = a2 + (n0 + 1) * 65;
        const unsigned long long* ap2 = a2 + (n0 + 2) * 65;
        const unsigned long long* ap3 = a2 + (n0 + 3) * 65;
#pragma unroll 4
        for (int kk = 0; kk < 64; kk++) {
            const float* wp = w_s + kk * 128;
            ulonglong2 w01 = *(const ulonglong2*)(wp + o0);
            ulonglong2 w23 = *(const ulonglong2*)(wp + 64 + o0);
            unsigned long long a0 = ap0[kk], a1 = ap1[kk];
            unsigned long long av2 = ap2[kk], a3 = ap3[kk];
            fma2(acc[0][0], a0, w01.x); fma2(acc[0][1], a0, w01.y);
            fma2(acc[0][2], a0, w23.x); fma2(acc[0][3], a0, w23.y);
            fma2(acc[1][0], a1, w01.x); fma2(acc[1][1], a1, w01.y);
            fma2(acc[1][2], a1, w23.x); fma2(acc[1][3], a1, w23.y);
            fma2(acc[2][0], av2, w01.x); fma2(acc[2][1], av2, w01.y);
            fma2(acc[2][2], av2, w23.x); fma2(acc[2][3], av2, w23.y);
            fma2(acc[3][0], a3, w01.x); fma2(acc[3][1], a3, w01.y);
            fma2(acc[3][2], a3, w23.x); fma2(acc[3][3], a3, w23.y);
        }
        __syncthreads();
    }

#pragma unroll
    for (int i = 0; i < 4; i++) {
        int g = base + n0 + i;
        if (g >= N_NODES) continue;
        float4 r0, r1;
        up2(acc[i][0], r0.x, r0.y); up2(acc[i][1], r0.z, r0.w);
        up2(acc[i][2], r1.x, r1.y); up2(acc[i][3], r1.z, r1.w);
        r0.x = fmaxf(r0.x, 0.f); r0.y = fmaxf(r0.y, 0.f);
        r0.z = fmaxf(r0.z, 0.f); r0.w = fmaxf(r0.w, 0.f);
        r1.x = fmaxf(r1.x, 0.f); r1.y = fmaxf(r1.y, 0.f);
        r1.z = fmaxf(r1.z, 0.f); r1.w = fmaxf(r1.w, 0.f);
        *(float4*)&g_h[(size_t)g * 128 + o0] = r0;
        *(float4*)&g_h[(size_t)g * 128 + 64 + o0] = r1;
    }
}

// ---------------------------------------------------------------------------
// Y kernel: y = h @ W2l^T  (K=128, 64 outs). Same tiling as gemm2.
// ---------------------------------------------------------------------------
#define G2_SMEM (128 * 65 * 8 + 64 * 64 * 4)

__global__ __launch_bounds__(256)
void y_kernel() {
    extern __shared__ unsigned long long sm_u[];
    unsigned long long* a2 = sm_u;              // [128][65]
    float* w_s = (float*)(sm_u + 128 * 65);     // [64][64]

    int tid = threadIdx.x;
    int base = blockIdx.x * 128;
    int tx = tid & 7, ty = tid >> 3;
    int n0 = ty * 4, o0 = tx * 4;

    unsigned long long acc[4][4];
#pragma unroll
    for (int i = 0; i < 4; i++)
#pragma unroll
        for (int j = 0; j < 4; j++) acc[i][j] = 0ull;

    for (int kt = 0; kt < 2; kt++) {
        int koff = kt * 64;
#pragma unroll
        for (int t = 0; t < 8; t++) {
            int idx = tid + t * 256;            // 0..2047
            int row = idx >> 4, c4 = idx & 15;
            int g = base + row;
            float4 v = make_float4(0.f, 0.f, 0.f, 0.f);
            if (g < N_NODES)
                v = ((const float4*)(g_h + (size_t)g * 128 + koff))[c4];
            unsigned long long* d = a2 + row * 65 + c4 * 4;
            d[0] = pk2(v.x, v.x); d[1] = pk2(v.y, v.y);
            d[2] = pk2(v.z, v.z); d[3] = pk2(v.w, v.w);
        }
        const float4* wsrc = (const float4*)(g_wt2 + kt * 64 * 64); // W2l rows
#pragma unroll
        for (int t = 0; t < 4; t++) {
            int idx = tid + t * 256;            // 0..1023
            ((float4*)w_s)[idx] = wsrc[idx];
        }
        __syncthreads();

        const unsigned long long* ap0 = a2 + (n0 + 0) * 65;
        const unsigned long long* ap1 = a2 + (n0 + 1) * 65;
        const unsigned long long* ap2 = a2 + (n0 + 2) * 65;
        const unsigned long long* ap3 = a2 + (n0 + 3) * 65;
#pragma unroll 4
        for (int kk = 0; kk < 64; kk++) {
            const float* wp = w_s + kk * 64;
            ulonglong2 w01 = *(const ulonglong2*)(wp + o0);
            ulonglong2 w23 = *(const ulonglong2*)(wp + 32 + o0);
            unsigned long long a0 = ap0[kk], a1 = ap1[kk];
            unsigned long long av2 = ap2[kk], a3 = ap3[kk];
            fma2(acc[0][0], a0, w01.x); fma2(acc[0][1], a0, w01.y);
            fma2(acc[0][2], a0, w23.x); fma2(acc[0][3], a0, w23.y);
            fma2(acc[1][0], a1, w01.x); fma2(acc[1][1], a1, w01.y);
            fma2(acc[1][2], a1, w23.x); fma2(acc[1][3], a1, w23.y);
            fma2(acc[2][0], av2, w01.x); fma2(acc[2][1], av2, w01.y);
            fma2(acc[2][2], av2, w23.x); fma2(acc[2][3], av2, w23.y);
            fma2(acc[3][0], a3, w01.x); fma2(acc[3][1], a3, w01.y);
            fma2(acc[3][2], a3, w23.x); fma2(acc[3][3], a3, w23.y);
        }
        __syncthreads();
    }

#pragma unroll
    for (int i = 0; i < 4; i++) {
        int g = base + n0 + i;
        if (g >= N_NODES) continue;
        float4 r0, r1;
        up2(acc[i][0], r0.x, r0.y); up2(acc[i][1], r0.z, r0.w);
        up2(acc[i][2], r1.x, r1.y); up2(acc[i][3], r1.z, r1.w);
        *(float4*)&g_y[(size_t)g * 64 + o0] = r0;
        *(float4*)&g_y[(size_t)g * 64 + 32 + o0] = r1;
    }
}

// ---------------------------------------------------------------------------
// GEMM2 + log_softmax: out = logsoftmax( aggY + h @ W2r^T + b2l ), K=128.
// ---------------------------------------------------------------------------
__global__ __launch_bounds__(256)
void gemm2_kernel(const float* __restrict__ bl, float* __restrict__ out) {
    extern __shared__ unsigned long long sm_u[];
    unsigned long long* a2 = sm_u;              // [128][65]
    float* w_s = (float*)(sm_u + 128 * 65);     // [64][64]

    int tid = threadIdx.x;
    int base = blockIdx.x * 128;
    int tx = tid & 7, ty = tid >> 3;
    int n0 = ty * 4, o0 = tx * 4;

    unsigned long long acc[4][4];
    {
        unsigned long long b0 = pk2(bl[o0], bl[o0 + 1]);
        unsigned long long b1 = pk2(bl[o0 + 2], bl[o0 + 3]);
        unsigned long long b2 = pk2(bl[32 + o0], bl[32 + o0 + 1]);
        unsigned long long b3 = pk2(bl[32 + o0 + 2], bl[32 + o0 + 3]);
#pragma unroll
        for (int i = 0; i < 4; i++) {
            acc[i][0] = b0; acc[i][1] = b1; acc[i][2] = b2; acc[i][3] = b3;
        }
    }

    for (int kt = 0; kt < 2; kt++) {
        int koff = kt * 64;
#pragma unroll
        for (int t = 0; t < 8; t++) {
            int idx = tid + t * 256;            // 0..2047
            int row = idx >> 4, c4 = idx & 15;
            int g = base + row;
            float4 v = make_float4(0.f, 0.f, 0.f, 0.f);
            if (g < N_NODES)
                v = ((const float4*)(g_h + (size_t)g * 128 + koff))[c4];
            unsigned long long* d = a2 + row * 65 + c4 * 4;
            d[0] = pk2(v.x, v.x); d[1] = pk2(v.y, v.y);
            d[2] = pk2(v.z, v.z); d[3] = pk2(v.w, v.w);
        }
        const float4* wsrc = (const float4*)(g_wt2 + (2 + kt) * 64 * 64); // W2r rows
#pragma unroll
        for (int t = 0; t < 4; t++) {
            int idx = tid + t * 256;            // 0..1023
            ((float4*)w_s)[idx] = wsrc[idx];
        }
        __syncthreads();

        const unsigned long long* ap0 = a2 + (n0 + 0) * 65;
        const unsigned long long* ap1 = a2 + (n0 + 1) * 65;
        const unsigned long long* ap2 = a2 + (n0 + 2) * 65;
        const unsigned long long* ap3 = a2 + (n0 + 3) * 65;
#pragma unroll 4
        for (int kk = 0; kk < 64; kk++) {
            const float* wp = w_s + kk * 64;
            ulonglong2 w01 = *(const ulonglong2*)(wp + o0);
            ulonglong2 w23 = *(const ulonglong2*)(wp + 32 + o0);
            unsigned long long a0 = ap0[kk], a1 = ap1[kk];
            unsigned long long av2 = ap2[kk], a3 = ap3[kk];
            fma2(acc[0][0], a0, w01.x); fma2(acc[0][1], a0, w01.y);
            fma2(acc[0][2], a0, w23.x); fma2(acc[0][3], a0, w23.y);
            fma2(acc[1][0], a1, w01.x); fma2(acc[1][1], a1, w01.y);
            fma2(acc[1][2], a1, w23.x); fma2(acc[1][3], a1, w23.y);
            fma2(acc[2][0], av2, w01.x); fma2(acc[2][1], av2, w01.y);
            fma2(acc[2][2], av2, w23.x); fma2(acc[2][3], av2, w23.y);
            fma2(acc[3][0], a3, w01.x); fma2(acc[3][1], a3, w01.y);
            fma2(acc[3][2], a3, w23.x); fma2(acc[3][3], a3, w23.y);
        }
        __syncthreads();
    }

#pragma unroll
    for (int i = 0; i < 4; i++) {
        int g = base + n0 + i;
        float v[8];
        up2(acc[i][0], v[0], v[1]); up2(acc[i][1], v[2], v[3]);
        up2(acc[i][2], v[4], v[5]); up2(acc[i][3], v[6], v[7]);
        // add pre-aggregated mean_agg(h @ W2l^T)
        if (g < N_NODES) {
            float4 t0 = *(const float4*)&g_aggy[(size_t)g * 64 + o0];
            float4 t1 = *(const float4*)&g_aggy[(size_t)g * 64 + 32 + o0];
            v[0] += t0.x; v[1] += t0.y; v[2] += t0.z; v[3] += t0.w;
            v[4] += t1.x; v[5] += t1.y; v[6] += t1.z; v[7] += t1.w;
        }
        float m = v[0];
#pragma unroll
        for (int j = 1; j < 8; j++) m = fmaxf(m, v[j]);
#pragma unroll
        for (int off = 1; off < 8; off <<= 1)
            m = fmaxf(m, __shfl_xor_sync(0xffffffffu, m, off));
        float s = 0.f;
#pragma unroll
        for (int j = 0; j < 8; j++) s += expf(v[j] - m);
#pragma unroll
        for (int off = 1; off < 8; off <<= 1)
            s += __shfl_xor_sync(0xffffffffu, s, off);
        float lse = m + logf(s);
        if (g < N_NODES) {
            float4 r0 = make_float4(v[0] - lse, v[1] - lse, v[2] - lse, v[3] - lse);
            float4 r1 = make_float4(v[4] - lse, v[5] - lse, v[6] - lse, v[7] - lse);
            *(float4*)&out[(size_t)g * 64 + o0] = r0;
            *(float4*)&out[(size_t)g * 64 + 32 + o0] = r1;
        }
    }
}

// ---------------------------------------------------------------------------
// Launch
// ---------------------------------------------------------------------------
extern "C" void kernel_launch(void* const* d_in, const int* in_sizes, int n_in,
                              void* d_out, int out_size) {
    const float* x   = (const float*)d_in[0];
    const void*  edg = d_in[1];
    const float* W1l = (const float*)d_in[2];
    const float* b1l = (const float*)d_in[3];
    const float* W1r = (const float*)d_in[4];
    const float* W2l = (const float*)d_in[5];
    const float* b2l = (const float*)d_in[6];
    const float* W2r = (const float*)d_in[7];
    float* out = (float*)d_out;

    int E = in_sizes[1] / 2;
    if (E > E_MAX) E = E_MAX;

    cudaFuncSetAttribute(gemm1_kernel,
                         cudaFuncAttributeMaxDynamicSharedMemorySize, G1_SMEM);
    cudaFuncSetAttribute(y_kernel,
                         cudaFuncAttributeMaxDynamicSharedMemorySize, G2_SMEM);
    cudaFuncSetAttribute(gemm2_kernel,
                         cudaFuncAttributeMaxDynamicSharedMemorySize, G2_SMEM);

    int eb = (E + 255) / 256;
    int g128_blocks = (N_NODES * 32 + 255) / 256;     // 12500
    int g64_blocks = (N_NODES * 16 + 255) / 256;      // 6250
    int g1_blocks = (N_NODES + 63) / 64;              // 1563
    int g2_blocks = (N_NODES + 127) / 128;            // 782

    setup_kernel<<<(N_NODES + 255) / 256, 256>>>((const unsigned int*)edg);
    hist_kernel<<<eb, 256>>>(edg, E);
    scan_sum_kernel<<<NBLK_SCAN, 1024>>>(W1l, W1r, W2l, W2r);
    scan_offsets_kernel<<<1, 128>>>();
    scan_write_kernel<<<NBLK_SCAN, 1024>>>();
    fill_kernel<<<eb, 256>>>(edg, E);

    gather128_kernel<<<g128_blocks, 256>>>(x);
    gemm1_kernel<<<g1_blocks, 256, G1_SMEM>>>(x, b1l);
    y_kernel<<<g2_blocks, 256, G2_SMEM>>>();
    gather64_kernel<<<g64_blocks, 256>>>();
    gemm2_kernel<<<g2_blocks, 256, G2_SMEM>>>(b2l, out);
}

// round 8
// speedup vs baseline: 4.4694x; 1.0993x over previous
#include <cuda_runtime.h>
#include <math.h>

#define N_NODES 100000
#define E_MAX   1600000
#define NBLK_SCAN 98   // ceil(N_NODES / 1024)

// ---------------------------------------------------------------------------
// Scratch (__device__ globals: allocation-free rule)
// ---------------------------------------------------------------------------
__device__ __align__(16) float g_agg[(size_t)N_NODES * 128]; // layer-1 mean
__device__ __align__(16) float g_y[(size_t)N_NODES * 64];    // h @ W2l^T
__device__ __align__(16) float g_z[(size_t)N_NODES * 64];    // h @ W2r^T + b2
__device__ int   g_row[N_NODES + 1];   // CSR row_ptr (by dst)
__device__ int   g_cur[N_NODES];       // counts, then fill cursor
__device__ int   g_col[E_MAX];         // CSR col (src ids)
__device__ float g_inv[N_NODES];       // 1/max(deg,1)
__device__ int   g_bsum[NBLK_SCAN];    // per-block sums for scan
__device__ int   g_boff[NBLK_SCAN];    // per-block exclusive offsets
__device__ __align__(16) float g_wt1[256 * 128]; // k-major [k][o]: W1l||W1r
__device__ __align__(16) float g_wt2[256 * 64];  // k-major [k][o]: W2l||W2r
__device__ int   g_is64;

// ---------------------------------------------------------------------------
// Packed f32x2 helpers (Blackwell FFMA2 — PTX-only)
// ---------------------------------------------------------------------------
__device__ __forceinline__ void fma2(unsigned long long& d,
                                     unsigned long long a,
                                     unsigned long long b) {
    asm("fma.rn.f32x2 %0, %1, %2, %0;" : "+l"(d) : "l"(a), "l"(b));
}
__device__ __forceinline__ unsigned long long pk2(float x, float y) {
    unsigned long long r;
    asm("mov.b64 %0, {%1, %2};" : "=l"(r) : "f"(x), "f"(y));
    return r;
}
__device__ __forceinline__ void up2(unsigned long long v, float& x, float& y) {
    asm("mov.b64 {%0, %1}, %2;" : "=f"(x), "=f"(y) : "l"(v));
}

// ---------------------------------------------------------------------------
// Setup: block 0 detects int64 vs int32 edges; all blocks zero g_cur.
// ---------------------------------------------------------------------------
__global__ void setup_kernel(const unsigned int* __restrict__ e) {
    int i = blockIdx.x * blockDim.x + threadIdx.x;
    if (i < N_NODES) g_cur[i] = 0;
    if (blockIdx.x == 0) {
        __shared__ int nz;
        if (threadIdx.x == 0) nz = 0;
        __syncthreads();
        unsigned int acc = 0;
        for (int j = threadIdx.x; j < 1024; j += blockDim.x)
            acc |= e[2 * j + 1];
        if (acc) atomicOr(&nz, 1);
        __syncthreads();
        if (threadIdx.x == 0) g_is64 = (nz == 0) ? 1 : 0;
    }
}

// ---------------------------------------------------------------------------
// CSR build: histogram -> 3-phase full-chip scan -> fill
// ---------------------------------------------------------------------------
__global__ void hist_kernel(const void* __restrict__ edges, int E) {
    int i = blockIdx.x * blockDim.x + threadIdx.x;
    if (i >= E) return;
    int d = g_is64 ? (int)((const long long*)edges)[E + i]
                   : ((const int*)edges)[E + i];
    atomicAdd(&g_cur[d], 1);
}

// Phase 1: per-block sums; also folds the weight transpose (independent work).
__global__ void scan_sum_kernel(const float* __restrict__ W1l,
                                const float* __restrict__ W1r,
                                const float* __restrict__ W2l,
                                const float* __restrict__ W2r) {
    __shared__ int wsum[32];
    int tid = threadIdx.x;
    int i = blockIdx.x * 1024 + tid;
    int c = (i < N_NODES) ? g_cur[i] : 0;
    int v = c;
#pragma unroll
    for (int off = 16; off; off >>= 1) v += __shfl_xor_sync(~0u, v, off);
    if ((tid & 31) == 0) wsum[tid >> 5] = v;

    // Weight transpose: 32768 + 16384 elements over 98*1024 threads
    if (i < 256 * 128) {
        int k = i >> 7, o = i & 127;
        g_wt1[i] = (k < 128) ? W1l[o * 128 + k] : W1r[o * 128 + (k - 128)];
    }
    {
        int j = i - 256 * 128;
        if (j >= 0 && j < 256 * 64) {
            int k = j >> 6, o = j & 63;
            g_wt2[j] = (k < 128) ? W2l[o * 128 + k] : W2r[o * 128 + (k - 128)];
        }
    }

    __syncthreads();
    if (tid < 32) {
        int s = wsum[tid];
#pragma unroll
        for (int off = 16; off; off >>= 1) s += __shfl_xor_sync(~0u, s, off);
        if (tid == 0) g_bsum[blockIdx.x] = s;
    }
}

// Phase 2: scan the 98 block sums (single 128-thread block)
__global__ void scan_offsets_kernel() {
    __shared__ int wsum[4];
    int tid = threadIdx.x;
    int lane = tid & 31, w = tid >> 5;
    int v = (tid < NBLK_SCAN) ? g_bsum[tid] : 0;
    int inc = v;
#pragma unroll
    for (int off = 1; off < 32; off <<= 1) {
        int t = __shfl_up_sync(~0u, inc, off);
        if (lane >= off) inc += t;
    }
    if (lane == 31) wsum[w] = inc;
    __syncthreads();
    int woff = 0;
    for (int j = 0; j < w; j++) woff += wsum[j];
    int excl = woff + inc - v;
    if (tid < NBLK_SCAN) g_boff[tid] = excl;
    if (tid == NBLK_SCAN - 1) g_row[N_NODES] = excl + v;
}

// Phase 3: block-local exclusive scan + offset; write row/cursor/inv
__global__ void scan_write_kernel() {
    __shared__ int wsum[32];
    int tid = threadIdx.x;
    int lane = tid & 31, w = tid >> 5;
    int i = blockIdx.x * 1024 + tid;
    int c = (i < N_NODES) ? g_cur[i] : 0;
    int inc = c;
#pragma unroll
    for (int off = 1; off < 32; off <<= 1) {
        int t = __shfl_up_sync(~0u, inc, off);
        if (lane >= off) inc += t;
    }
    if (lane == 31) wsum[w] = inc;
    __syncthreads();
    if (tid < 32) {
        int v = wsum[tid];
        int winc = v;
#pragma unroll
        for (int off = 1; off < 32; off <<= 1) {
            int t = __shfl_up_sync(~0u, winc, off);
            if (tid >= off) winc += t;
        }
        wsum[tid] = winc - v;   // exclusive warp offset
    }
    __syncthreads();
    int excl = g_boff[blockIdx.x] + wsum[w] + inc - c;
    if (i < N_NODES) {
        g_row[i] = excl;
        g_cur[i] = excl;
        g_inv[i] = 1.0f / (float)max(c, 1);
    }
}

__global__ void fill_kernel(const void* __restrict__ edges, int E) {
    int i = blockIdx.x * blockDim.x + threadIdx.x;
    if (i >= E) return;
    int s, d;
    if (g_is64) {
        const long long* p = (const long long*)edges;
        s = (int)p[i]; d = (int)p[E + i];
    } else {
        const int* p = (const int*)edges;
        s = p[i]; d = p[E + i];
    }
    int pos = atomicAdd(&g_cur[d], 1);
    g_col[pos] = s;
}

// ---------------------------------------------------------------------------
// Gather-mean (128-wide): one warp per node, lane = one float4 chunk.
// ---------------------------------------------------------------------------
__global__ void gather128_kernel(const float* __restrict__ x) {
    int wid = (blockIdx.x * blockDim.x + threadIdx.x) >> 5;
    int lane = threadIdx.x & 31;
    if (wid >= N_NODES) return;
    const float4* base = (const float4*)x;
    int beg = g_row[wid], end = g_row[wid + 1];
    float4 acc = make_float4(0.f, 0.f, 0.f, 0.f);
    int i = beg;
    for (; i + 2 <= end; i += 2) {
        int s0 = g_col[i], s1 = g_col[i + 1];
        float4 v0 = base[(size_t)s0 * 32 + lane];
        float4 v1 = base[(size_t)s1 * 32 + lane];
        acc.x += v0.x + v1.x; acc.y += v0.y + v1.y;
        acc.z += v0.z + v1.z; acc.w += v0.w + v1.w;
    }
    if (i < end) {
        int s = g_col[i];
        float4 v = base[(size_t)s * 32 + lane];
        acc.x += v.x; acc.y += v.y; acc.z += v.z; acc.w += v.w;
    }
    float inv = g_inv[wid];
    ((float4*)g_agg)[(size_t)wid * 32 + lane] =
        make_float4(acc.x * inv, acc.y * inv, acc.z * inv, acc.w * inv);
}

// ---------------------------------------------------------------------------
// Fused GEMM1 + y/z projections:
//   h = relu( [mean||x] @ Wt1 + b1l )   (kept block-resident, never stored)
//   y = h @ W2l^T          -> g_y
//   z = h @ W2r^T + b2l    -> g_z
// Block 64 nodes x 128 outs, BK=64, 256 threads. Phase 2 reuses the same
// smem buffers, staging h dup-pairs + W2 halves in two K=64 passes.
// ---------------------------------------------------------------------------
#define G1_SMEM (64 * 65 * 8 + 64 * 128 * 4)

__global__ __launch_bounds__(256)
void gemm1_fused_kernel(const float* __restrict__ x,
                        const float* __restrict__ bl,
                        const float* __restrict__ b2) {
    extern __shared__ unsigned long long sm_u[];
    unsigned long long* a2 = sm_u;              // [64][65] dup pairs
    float* w_s = (float*)(sm_u + 64 * 65);      // [64][128]

    int tid = threadIdx.x;
    int base = blockIdx.x * 64;
    int tx = tid & 15, ty = tid >> 4;
    int n0 = ty * 4, o0 = tx * 4;

    unsigned long long acc[4][4];
    {
        unsigned long long b0 = pk2(bl[o0], bl[o0 + 1]);
        unsigned long long b1 = pk2(bl[o0 + 2], bl[o0 + 3]);
        unsigned long long b2p = pk2(bl[64 + o0], bl[64 + o0 + 1]);
        unsigned long long b3 = pk2(bl[64 + o0 + 2], bl[64 + o0 + 3]);
#pragma unroll
        for (int i = 0; i < 4; i++) {
            acc[i][0] = b0; acc[i][1] = b1; acc[i][2] = b2p; acc[i][3] = b3;
        }
    }

    for (int kt = 0; kt < 4; kt++) {
        const float* asrc = (kt < 2) ? g_agg : x;
        int koff = (kt & 1) * 64;
#pragma unroll
        for (int t = 0; t < 4; t++) {
            int idx = tid + t * 256;            // 0..1023
            int row = idx >> 4, c4 = idx & 15;
            int g = base + row;
            float4 v = make_float4(0.f, 0.f, 0.f, 0.f);
            if (g < N_NODES)
                v = ((const float4*)(asrc + (size_t)g * 128 + koff))[c4];
            unsigned long long* d = a2 + row * 65 + c4 * 4;
            d[0] = pk2(v.x, v.x); d[1] = pk2(v.y, v.y);
            d[2] = pk2(v.z, v.z); d[3] = pk2(v.w, v.w);
        }
        const float4* wsrc = (const float4*)(g_wt1 + kt * 64 * 128);
#pragma unroll
        for (int t = 0; t < 8; t++) {
            int idx = tid + t * 256;            // 0..2047
            ((float4*)w_s)[idx] = wsrc[idx];
        }
        __syncthreads();

        const unsigned long long* ap0 = a2 + (n0 + 0) * 65;
        const unsigned long long* ap1 = a2 + (n0 + 1) * 65;
        const unsigned long long* ap2 = a2 + (n0 + 2) * 65;
        const unsigned long long* ap3 = a2 + (n0 + 3) * 65;
#pragma unroll 4
        for (int kk = 0; kk < 64; kk++) {
            const float* wp = w_s + kk * 128;
            ulonglong2 w01 = *(const ulonglong2*)(wp + o0);
            ulonglong2 w23 = *(const ulonglong2*)(wp + 64 + o0);
            unsigned long long a0 = ap0[kk], a1 = ap1[kk];
            unsigned long long av2 = ap2[kk], a3 = ap3[kk];
            fma2(acc[0][0], a0, w01.x); fma2(acc[0][1], a0, w01.y);
            fma2(acc[0][2], a0, w23.x); fma2(acc[0][3], a0, w23.y);
            fma2(acc[1][0], a1, w01.x); fma2(acc[1][1], a1, w01.y);
            fma2(acc[1][2], a1, w23.x); fma2(acc[1][3], a1, w23.y);
            fma2(acc[2][0], av2, w01.x); fma2(acc[2][1], av2, w01.y);
            fma2(acc[2][2], av2, w23.x); fma2(acc[2][3], av2, w23.y);
            fma2(acc[3][0], a3, w01.x); fma2(acc[3][1], a3, w01.y);
            fma2(acc[3][2], a3, w23.x); fma2(acc[3][3], a3, w23.y);
        }
        __syncthreads();
    }

    // relu'd h, block-resident: thread holds 4 nodes x 8 outs
    float hv[4][8];
#pragma unroll
    for (int i = 0; i < 4; i++) {
        up2(acc[i][0], hv[i][0], hv[i][1]); up2(acc[i][1], hv[i][2], hv[i][3]);
        up2(acc[i][2], hv[i][4], hv[i][5]); up2(acc[i][3], hv[i][6], hv[i][7]);
#pragma unroll
        for (int j = 0; j < 8; j++) hv[i][j] = fmaxf(hv[i][j], 0.f);
    }

    // Phase 2: y (outs 0..63 <- W2l) and z (outs 64..127 <- W2r), K=128 in 2 halves
    unsigned long long acc2[4][4];
#pragma unroll
    for (int i = 0; i < 4; i++)
#pragma unroll
        for (int j = 0; j < 4; j++) acc2[i][j] = 0ull;

#pragma unroll
    for (int kh = 0; kh < 2; kh++) {
        // stage h dup-pairs: thread's outs (kh half) become k-columns
#pragma unroll
        for (int i = 0; i < 4; i++) {
            unsigned long long* d = a2 + (n0 + i) * 65 + o0;
            // k index = o0+j ; value = hv[i][kh*4..kh*4+3] maps outs o0.. (kh=0)
            // and 64+o0.. (kh=1): both land at k-col o0+j within their half.
            d[0] = pk2(hv[i][kh * 4 + 0], hv[i][kh * 4 + 0]);
            d[1] = pk2(hv[i][kh * 4 + 1], hv[i][kh * 4 + 1]);
            d[2] = pk2(hv[i][kh * 4 + 2], hv[i][kh * 4 + 2]);
            d[3] = pk2(hv[i][kh * 4 + 3], hv[i][kh * 4 + 3]);
        }
        // stage combined W2 half: w_s[kk][o], o<64 = W2l, o>=64 = W2r
#pragma unroll
        for (int t = 0; t < 8; t++) {
            int idx = tid + t * 256;            // 0..2047 float4s
            int kk = idx >> 5, o4 = idx & 31;
            float4 wv;
            if (o4 < 16)
                wv = *(const float4*)&g_wt2[(kh * 64 + kk) * 64 + o4 * 4];
            else
                wv = *(const float4*)&g_wt2[(128 + kh * 64 + kk) * 64 + (o4 - 16) * 4];
            ((float4*)w_s)[idx] = wv;
        }
        __syncthreads();

        const unsigned long long* ap0 = a2 + (n0 + 0) * 65;
        const unsigned long long* ap1 = a2 + (n0 + 1) * 65;
        const unsigned long long* ap2 = a2 + (n0 + 2) * 65;
        const unsigned long long* ap3 = a2 + (n0 + 3) * 65;
#pragma unroll 4
        for (int kk = 0; kk < 64; kk++) {
            const float* wp = w_s + kk * 128;
            ulonglong2 w01 = *(const ulonglong2*)(wp + o0);          // y outs
            ulonglong2 w23 = *(const ulonglong2*)(wp + 64 + o0);     // z outs
            unsigned long long a0 = ap0[kk], a1 = ap1[kk];
            unsigned long long av2 = ap2[kk], a3 = ap3[kk];
            fma2(acc2[0][0], a0, w01.x); fma2(acc2[0][1], a0, w01.y);
            fma2(acc2[0][2], a0, w23.x); fma2(acc2[0][3], a0, w23.y);
            fma2(acc2[1][0], a1, w01.x); fma2(acc2[1][1], a1, w01.y);
            fma2(acc2[1][2], a1, w23.x); fma2(acc2[1][3], a1, w23.y);
            fma2(acc2[2][0], av2, w01.x); fma2(acc2[2][1], av2, w01.y);
            fma2(acc2[2][2], av2, w23.x); fma2(acc2[2][3], av2, w23.y);
            fma2(acc2[3][0], a3, w01.x); fma2(acc2[3][1], a3, w01.y);
            fma2(acc2[3][2], a3, w23.x); fma2(acc2[3][3], a3, w23.y);
        }
        __syncthreads();
    }

    float bz0 = b2[o0], bz1 = b2[o0 + 1], bz2 = b2[o0 + 2], bz3 = b2[o0 + 3];
#pragma unroll
    for (int i = 0; i < 4; i++) {
        int g = base + n0 + i;
        if (g >= N_NODES) continue;
        float4 ry, rz;
        up2(acc2[i][0], ry.x, ry.y); up2(acc2[i][1], ry.z, ry.w);
        up2(acc2[i][2], rz.x, rz.y); up2(acc2[i][3], rz.z, rz.w);
        rz.x += bz0; rz.y += bz1; rz.z += bz2; rz.w += bz3;
        *(float4*)&g_y[(size_t)g * 64 + o0] = ry;
        *(float4*)&g_z[(size_t)g * 64 + o0] = rz;
    }
}

// ---------------------------------------------------------------------------
// Gather-mean (64-wide over g_y) + z add + fused log_softmax -> out.
// 16 lanes per node, lane = one float4 (4 classes). 6250 blocks x 256.
// ---------------------------------------------------------------------------
__global__ void gather64_softmax_kernel(float* __restrict__ out) {
    int nid = (blockIdx.x * blockDim.x + threadIdx.x) >> 4;
    int lane = threadIdx.x & 15;
    if (nid >= N_NODES) return;
    const float4* base = (const float4*)g_y;
    int beg = g_row[nid], end = g_row[nid + 1];
    float4 acc = make_float4(0.f, 0.f, 0.f, 0.f);
    int i = beg;
    for (; i + 2 <= end; i += 2) {
        int s0 = g_col[i], s1 = g_col[i + 1];
        float4 v0 = base[(size_t)s0 * 16 + lane];
        float4 v1 = base[(size_t)s1 * 16 + lane];
        acc.x += v0.x + v1.x; acc.y += v0.y + v1.y;
        acc.z += v0.z + v1.z; acc.w += v0.w + v1.w;
    }
    if (i < end) {
        int s = g_col[i];
        float4 v = base[(size_t)s * 16 + lane];
        acc.x += v.x; acc.y += v.y; acc.z += v.z; acc.w += v.w;
    }
    float inv = g_inv[nid];
    float4 zv = ((const float4*)g_z)[(size_t)nid * 16 + lane];
    float4 v = make_float4(acc.x * inv + zv.x, acc.y * inv + zv.y,
                           acc.z * inv + zv.z, acc.w * inv + zv.w);

    // log_softmax over 64 classes: 16-lane group reduce (offsets 1,2,4,8)
    float m = fmaxf(fmaxf(v.x, v.y), fmaxf(v.z, v.w));
#pragma unroll
    for (int off = 1; off < 16; off <<= 1)
        m = fmaxf(m, __shfl_xor_sync(0xffffffffu, m, off));
    float s = expf(v.x - m) + expf(v.y - m) + expf(v.z - m) + expf(v.w - m);
#pragma unroll
    for (int off = 1; off < 16; off <<= 1)
        s += __shfl_xor_sync(0xffffffffu, s, off);
    float lse = m + logf(s);
    ((float4*)out)[(size_t)nid * 16 + lane] =
        make_float4(v.x - lse, v.y - lse, v.z - lse, v.w - lse);
}

// ---------------------------------------------------------------------------
// Launch
// ---------------------------------------------------------------------------
extern "C" void kernel_launch(void* const* d_in, const int* in_sizes, int n_in,
                              void* d_out, int out_size) {
    const float* x   = (const float*)d_in[0];
    const void*  edg = d_in[1];
    const float* W1l = (const float*)d_in[2];
    const float* b1l = (const float*)d_in[3];
    const float* W1r = (const float*)d_in[4];
    const float* W2l = (const float*)d_in[5];
    const float* b2l = (const float*)d_in[6];
    const float* W2r = (const float*)d_in[7];
    float* out = (float*)d_out;

    int E = in_sizes[1] / 2;
    if (E > E_MAX) E = E_MAX;

    cudaFuncSetAttribute(gemm1_fused_kernel,
                         cudaFuncAttributeMaxDynamicSharedMemorySize, G1_SMEM);

    int eb = (E + 255) / 256;
    int g128_blocks = (N_NODES * 32 + 255) / 256;     // 12500
    int g64_blocks = (N_NODES * 16 + 255) / 256;      // 6250
    int g1_blocks = (N_NODES + 63) / 64;              // 1563

    setup_kernel<<<(N_NODES + 255) / 256, 256>>>((const unsigned int*)edg);
    hist_kernel<<<eb, 256>>>(edg, E);
    scan_sum_kernel<<<NBLK_SCAN, 1024>>>(W1l, W1r, W2l, W2r);
    scan_offsets_kernel<<<1, 128>>>();
    scan_write_kernel<<<NBLK_SCAN, 1024>>>();
    fill_kernel<<<eb, 256>>>(edg, E);

    gather128_kernel<<<g128_blocks, 256>>>(x);
    gemm1_fused_kernel<<<g1_blocks, 256, G1_SMEM>>>(x, b1l, b2l);
    gather64_softmax_kernel<<<g64_blocks, 256>>>(out);
}